// round 9
// baseline (speedup 1.0000x reference)
#include <cuda_runtime.h>
#include <cuda_fp16.h>

// Problem constants
#define BB 2
#define SS 2048
#define DD 1024

// fp16 staging buffers + compaction lists (device globals: no allocation)
__device__ __half g_Q[BB * SS * DD];   // compacted unmasked Q rows
__device__ __half g_K[BB * SS * DD];
__device__ __half g_V[BB * SS * DD];
__device__ __half g_Xh[3][BB * SS * DD];
__device__ __half g_Wh[3][DD * DD];
__device__ int g_qidx[BB][SS];  // unmasked query indices (ascending)
__device__ int g_midx[BB][SS];  // masked query indices
__device__ int g_ncnt[BB];      // # unmasked
__device__ int g_mcnt[BB];      // # masked

// ---------- helpers ----------
__device__ __forceinline__ unsigned sptr(const void* p) {
    return (unsigned)__cvta_generic_to_shared(p);
}
__device__ __forceinline__ void ldsm4(unsigned& r0, unsigned& r1, unsigned& r2, unsigned& r3,
                                      unsigned addr) {
    asm volatile("ldmatrix.sync.aligned.m8n8.x4.shared.b16 {%0,%1,%2,%3}, [%4];"
                 : "=r"(r0), "=r"(r1), "=r"(r2), "=r"(r3)
                 : "r"(addr));
}
__device__ __forceinline__ void ldsm4t(unsigned& r0, unsigned& r1, unsigned& r2, unsigned& r3,
                                       unsigned addr) {
    asm volatile("ldmatrix.sync.aligned.m8n8.x4.trans.shared.b16 {%0,%1,%2,%3}, [%4];"
                 : "=r"(r0), "=r"(r1), "=r"(r2), "=r"(r3)
                 : "r"(addr));
}
__device__ __forceinline__ void mma16(float c[4], const unsigned a[4], unsigned b0, unsigned b1) {
    asm volatile(
        "mma.sync.aligned.m16n8k16.row.col.f32.f16.f16.f32 "
        "{%0,%1,%2,%3},{%4,%5,%6,%7},{%8,%9},{%0,%1,%2,%3};"
        : "+f"(c[0]), "+f"(c[1]), "+f"(c[2]), "+f"(c[3])
        : "r"(a[0]), "r"(a[1]), "r"(a[2]), "r"(a[3]), "r"(b0), "r"(b1));
}
__device__ __forceinline__ void cpa16(unsigned s, const void* g) {
    asm volatile("cp.async.cg.shared.global [%0], [%1], 16;" ::"r"(s), "l"(g));
}
__device__ __forceinline__ unsigned h2u(float a, float b) {
    __half2 h = __floats2half2_rn(a, b);
    return *(unsigned*)&h;
}
__device__ __forceinline__ float ex2(float x) {
    float y;
    asm("ex2.approx.ftz.f32 %0, %1;" : "=f"(y) : "f"(x));
    return y;
}

// =====================================================================
// Mask compaction: one warp per batch, ballot-based stable partition.
// =====================================================================
__global__ void compact_kernel(const int* __restrict__ amask) {
    const int b = blockIdx.x;
    const int lane = threadIdx.x;
    int nu = 0, nm = 0;
    for (int i0 = 0; i0 < SS; i0 += 32) {
        int m = amask[b * SS + i0 + lane] != 0;
        unsigned bal = __ballot_sync(0xffffffffu, m);
        unsigned below = (1u << lane) - 1u;
        if (m)
            g_qidx[b][nu + __popc(bal & below)] = i0 + lane;
        else
            g_midx[b][nm + __popc(~bal & below)] = i0 + lane;
        nu += __popc(bal);
        nm += 32 - __popc(bal);
    }
    if (lane == 0) { g_ncnt[b] = nu; g_mcnt[b] = nm; }
}

// =====================================================================
// fp32 -> fp16 conversion pass (bandwidth-bound)
// =====================================================================
__global__ void __launch_bounds__(256) cvt_kernel(
    const float* __restrict__ q, const float* __restrict__ k, const float* __restrict__ v,
    const float* __restrict__ wq, const float* __restrict__ wk, const float* __restrict__ wv) {
    const int sel = blockIdx.y;
    const float* src;
    __half* dst;
    int n4;
    switch (sel) {
        case 0: src = q;  dst = g_Xh[0]; n4 = BB * SS * DD / 4; break;
        case 1: src = k;  dst = g_Xh[1]; n4 = BB * SS * DD / 4; break;
        case 2: src = v;  dst = g_Xh[2]; n4 = BB * SS * DD / 4; break;
        case 3: src = wq; dst = g_Wh[0]; n4 = DD * DD / 4; break;
        case 4: src = wk; dst = g_Wh[1]; n4 = DD * DD / 4; break;
        default: src = wv; dst = g_Wh[2]; n4 = DD * DD / 4; break;
    }
    const int stride = gridDim.x * blockDim.x;
    for (int i = blockIdx.x * blockDim.x + threadIdx.x; i < n4; i += stride) {
        float4 f = ((const float4*)src)[i];
        __half2 h0 = __floats2half2_rn(f.x, f.y);
        __half2 h1 = __floats2half2_rn(f.z, f.w);
        uint2 o;
        o.x = *(unsigned*)&h0;
        o.y = *(unsigned*)&h1;
        ((uint2*)dst)[i] = o;
    }
}

// =====================================================================
// QKV projection (fp16): out = relu(X @ W^T + b). z=0 (Q) processes only
// unmasked rows (gathered input, compacted output). 3-stage cp.async.
// =====================================================================
#define QST 72
#define QSTG (128 * QST)
#define GEMM_SMEM (6 * QSTG * 2)

__global__ void __launch_bounds__(256, 2) qkv_gemm(
    const float* __restrict__ bq, const float* __restrict__ bk, const float* __restrict__ bv) {
    const int z = blockIdx.z;
    const __half* X = g_Xh[z];
    const __half* W = g_Wh[z];
    const float* bias = (z == 0) ? bq : (z == 1) ? bk : bv;
    __half* out = (z == 0) ? g_Q : (z == 1) ? g_K : g_V;

    const int tid = threadIdx.x;
    const int my = blockIdx.y;
    const int crow = tid >> 1;        // loader row within tile
    const int ccol = (tid & 1) * 32;  // loader col (halves)

    int obase, grow;
    if (z == 0) {
        const int bqb = my >> 4, tq = my & 15;
        const int nu = g_ncnt[bqb];
        if (tq * 128 >= nu) return;  // inactive tile (whole block exits)
        obase = bqb * 2048 + tq * 128;
        int i = tq * 128 + crow;
        if (i >= nu) i = nu - 1;  // clamp: duplicate last row (finite, discarded)
        grow = bqb * 2048 + g_qidx[bqb][i];
    } else {
        obase = my * 128;
        grow = my * 128 + crow;
    }

    extern __shared__ __align__(16) char smraw[];
    __half* XB = (__half*)smraw;
    __half* WB = (__half*)smraw + 3 * QSTG;

    const int warp = tid >> 5, lane = tid & 31;
    const int g = lane >> 2, tig = lane & 3;
    const int m0 = (warp >> 1) * 32;
    const int n0 = (warp & 1) * 64;
    const int bn = blockIdx.x * 128;

    const unsigned xdst = sptr(&XB[crow * QST + ccol]);
    const unsigned wdst = sptr(&WB[crow * QST + ccol]);
    const size_t xrow = (size_t)grow * 1024 + ccol;
    const size_t wrow = (size_t)(bn + crow) * 1024 + ccol;

    float acc[2][8][4];
#pragma unroll
    for (int mt = 0; mt < 2; mt++)
#pragma unroll
        for (int nt = 0; nt < 8; nt++)
#pragma unroll
            for (int i = 0; i < 4; i++) acc[mt][nt][i] = 0.0f;

    const unsigned xa0 = sptr(&XB[(m0 + (lane & 15)) * QST + (lane >> 4) * 8]);
    const unsigned xa1 = sptr(&XB[(m0 + 16 + (lane & 15)) * QST + (lane >> 4) * 8]);
    const unsigned wbb = sptr(&WB[(n0 + 8 * (lane >> 4) + (lane & 7)) * QST + ((lane >> 3) & 1) * 8]);

#pragma unroll
    for (int p = 0; p < 2; p++) {
        const unsigned soff = p * (QSTG * 2);
        const int k0 = p * 64;
#pragma unroll
        for (int c = 0; c < 4; c++) {
            cpa16(xdst + soff + c * 16, X + xrow + k0 + c * 8);
            cpa16(wdst + soff + c * 16, W + wrow + k0 + c * 8);
        }
        asm volatile("cp.async.commit_group;");
    }

    int st = 0, st2 = 2;
    for (int it = 0; it < 16; it++) {
        asm volatile("cp.async.wait_group 1;" ::: "memory");
        __syncthreads();

        if (it + 2 < 16) {
            const int k0 = (it + 2) * 64;
            const unsigned soff = st2 * (QSTG * 2);
#pragma unroll
            for (int c = 0; c < 4; c++) {
                cpa16(xdst + soff + c * 16, X + xrow + k0 + c * 8);
                cpa16(wdst + soff + c * 16, W + wrow + k0 + c * 8);
            }
        }
        asm volatile("cp.async.commit_group;");

        const unsigned sa = st * (QSTG * 2);
#pragma unroll
        for (int ks = 0; ks < 4; ks++) {
            unsigned a0[4], a1[4];
            ldsm4(a0[0], a0[1], a0[2], a0[3], xa0 + sa + ks * 32);
            ldsm4(a1[0], a1[1], a1[2], a1[3], xa1 + sa + ks * 32);
#pragma unroll
            for (int j = 0; j < 4; j++) {
                unsigned b[4];
                ldsm4(b[0], b[1], b[2], b[3], wbb + sa + j * (16 * QST * 2) + ks * 32);
                mma16(acc[0][2 * j], a0, b[0], b[1]);
                mma16(acc[0][2 * j + 1], a0, b[2], b[3]);
                mma16(acc[1][2 * j], a1, b[0], b[1]);
                mma16(acc[1][2 * j + 1], a1, b[2], b[3]);
            }
        }
        st = (st == 2) ? 0 : st + 1;
        st2 = (st2 == 2) ? 0 : st2 + 1;
    }

#pragma unroll
    for (int nt = 0; nt < 8; nt++) {
        int n = bn + n0 + 8 * nt + 2 * tig;
        float b0 = __ldg(&bias[n]), b1 = __ldg(&bias[n + 1]);
#pragma unroll
        for (int mt = 0; mt < 2; mt++) {
            int m = obase + m0 + 16 * mt + g;
            float v0 = acc[mt][nt][0] + b0, v1 = acc[mt][nt][1] + b1;
            v0 = v0 > 0.f ? v0 : 0.f;
            v1 = v1 > 0.f ? v1 : 0.f;
            *(__half2*)&out[(size_t)m * 1024 + n] = __floats2half2_rn(v0, v1);
            float v2 = acc[mt][nt][2] + b0, v3 = acc[mt][nt][3] + b1;
            v2 = v2 > 0.f ? v2 : 0.f;
            v3 = v3 > 0.f ? v3 : 0.f;
            *(__half2*)&out[(size_t)(m + 8) * 1024 + n] = __floats2half2_rn(v2, v3);
        }
    }
}

// =====================================================================
// Masked rows: out = rowmean(V per (b,h)) + residual (uniform softmax).
// =====================================================================
__global__ void __launch_bounds__(256) vmean_kernel(const float* __restrict__ queries,
                                                    float* __restrict__ out) {
    __shared__ float part[4][64];
    const int h = blockIdx.x, b = blockIdx.y;
    const int d = threadIdx.x & 63, ch = threadIdx.x >> 6;

    float sum = 0.0f;
    const __half* vp = g_V + (size_t)(b * 2048 + ch * 512) * 1024 + h * 64 + d;
    for (int k = 0; k < 512; k++) sum += __half2float(vp[(size_t)k * 1024]);
    part[ch][d] = sum;
    __syncthreads();
    const float mv = (part[0][d] + part[1][d] + part[2][d] + part[3][d]) * (1.0f / 2048.0f);

    const int nm = g_mcnt[b];
    for (int j = ch; j < nm; j += 4) {
        const int q = g_midx[b][j];
        const int srow = 128 * h + 2 * d + (q >> 10);
        const size_t off = (size_t)(b * 2048 + srow) * 1024 + (q & 1023);
        out[off] = mv + queries[off];
    }
}

// =====================================================================
// Flash attention over COMPACTED unmasked queries (no mask term), with
// scattered scrambled-reshape epilogue + residual.
// =====================================================================
#define KST 72
#define OST 68
#define STAGE_H (64 * KST)
#define ATTN_SMEM ((6 * STAGE_H + 128 * KST) * 2)

__global__ void __launch_bounds__(256) attn_mma(const float* __restrict__ queries,
                                                float* __restrict__ out) {
    const int b = blockIdx.z, h = blockIdx.y;
    const int q0 = blockIdx.x * 128;
    const int nu = g_ncnt[b];
    if (q0 >= nu) return;  // inactive tile

    extern __shared__ __align__(16) char smbase[];
    __half* KB = (__half*)smbase;
    __half* VB = (__half*)smbase + 3 * STAGE_H;
    __half* Qs = (__half*)smbase + 6 * STAGE_H;
    float* So = (float*)smbase;
    __shared__ int sidx[128];

    const int tid = threadIdx.x;
    const int warp = tid >> 5, lane = tid & 31;
    const int g = lane >> 2, tig = lane & 3;
    const int qw = warp * 16;

    if (tid < 128) sidx[tid] = (q0 + tid < nu) ? g_qidx[b][q0 + tid] : -1;

    const int crow = tid >> 2;
    const int ccol = (tid & 3) * 16;
    const unsigned kdst = sptr(&KB[crow * KST + ccol]);
    const unsigned vdst = sptr(&VB[crow * KST + ccol]);

#pragma unroll
    for (int p = 0; p < 2; p++) {
        const size_t gofs = (size_t)(b * 2048 + p * 64 + crow) * 1024 + h * 64 + ccol;
        const unsigned soff = p * (STAGE_H * 2);
        cpa16(kdst + soff, g_K + gofs);
        cpa16(kdst + soff + 16, g_K + gofs + 8);
        cpa16(vdst + soff, g_V + gofs);
        cpa16(vdst + soff + 16, g_V + gofs + 8);
        asm volatile("cp.async.commit_group;");
    }

    // stage Q (compacted rows; scaled by 0.125*log2e), frags to registers
    {
        int row = tid >> 1;
        int koff = (tid & 1) * 32;
        const __half* qsrc = g_Q + (size_t)(b * 2048 + q0 + row) * 1024 + h * 64 + koff;
        const float qs = 0.125f * 1.4426950408889634f;
        const __half2 sc = __floats2half2_rn(qs, qs);
        __half2 v[16];
        *(uint4*)&v[0] = *(const uint4*)&qsrc[0];
        *(uint4*)&v[4] = *(const uint4*)&qsrc[8];
        *(uint4*)&v[8] = *(const uint4*)&qsrc[16];
        *(uint4*)&v[12] = *(const uint4*)&qsrc[24];
#pragma unroll
        for (int j = 0; j < 16; j++) v[j] = __hmul2(v[j], sc);
        *(uint4*)&Qs[row * KST + koff] = *(uint4*)&v[0];
        *(uint4*)&Qs[row * KST + koff + 8] = *(uint4*)&v[4];
        *(uint4*)&Qs[row * KST + koff + 16] = *(uint4*)&v[8];
        *(uint4*)&Qs[row * KST + koff + 24] = *(uint4*)&v[12];
    }
    __syncwarp();
    unsigned qf[4][4];
    {
        unsigned qa = sptr(&Qs[(qw + (lane & 15)) * KST + (lane >> 4) * 8]);
#pragma unroll
        for (int ks = 0; ks < 4; ks++)
            ldsm4(qf[ks][0], qf[ks][1], qf[ks][2], qf[ks][3], qa + ks * 32);
    }

    float mA = -1e30f, mB = -1e30f, lA = 0.0f, lB = 0.0f;
    float o[8][4];
#pragma unroll
    for (int nt = 0; nt < 8; nt++)
#pragma unroll
        for (int i = 0; i < 4; i++) o[nt][i] = 0.0f;

    const unsigned kb0 = sptr(&KB[(8 * (lane >> 4) + (lane & 7)) * KST + ((lane >> 3) & 1) * 8]);
    const unsigned vb0 = sptr(&VB[(8 * ((lane >> 3) & 1) + (lane & 7)) * KST + (lane >> 4) * 8]);

    int st = 0, st2 = 2;
    for (int jt = 0; jt < 32; jt++) {
        asm volatile("cp.async.wait_group 1;" ::: "memory");
        __syncthreads();

        if (jt + 2 < 32) {
            const size_t gofs = (size_t)(b * 2048 + (jt + 2) * 64 + crow) * 1024 + h * 64 + ccol;
            const unsigned soff = st2 * (STAGE_H * 2);
            cpa16(kdst + soff, g_K + gofs);
            cpa16(kdst + soff + 16, g_K + gofs + 8);
            cpa16(vdst + soff, g_V + gofs);
            cpa16(vdst + soff + 16, g_V + gofs + 8);
        }
        asm volatile("cp.async.commit_group;");

        const unsigned kb = kb0 + st * (STAGE_H * 2);
        float s[8][4];
#pragma unroll
        for (int nt = 0; nt < 8; nt++)
#pragma unroll
            for (int i = 0; i < 4; i++) s[nt][i] = 0.0f;
#pragma unroll
        for (int ks = 0; ks < 4; ks++) {
#pragma unroll
            for (int j = 0; j < 4; j++) {
                unsigned bfr[4];
                ldsm4(bfr[0], bfr[1], bfr[2], bfr[3], kb + j * (16 * KST * 2) + ks * 32);
                mma16(s[2 * j], qf[ks], bfr[0], bfr[1]);
                mma16(s[2 * j + 1], qf[ks], bfr[2], bfr[3]);
            }
        }

        float mxA = s[0][0], mxB = s[0][2];
#pragma unroll
        for (int nt = 0; nt < 8; nt++) {
            mxA = fmaxf(mxA, fmaxf(s[nt][0], s[nt][1]));
            mxB = fmaxf(mxB, fmaxf(s[nt][2], s[nt][3]));
        }
        mxA = fmaxf(mxA, __shfl_xor_sync(0xffffffffu, mxA, 1));
        mxA = fmaxf(mxA, __shfl_xor_sync(0xffffffffu, mxA, 2));
        mxB = fmaxf(mxB, __shfl_xor_sync(0xffffffffu, mxB, 1));
        mxB = fmaxf(mxB, __shfl_xor_sync(0xffffffffu, mxB, 2));
        float mnA = fmaxf(mA, mxA), mnB = fmaxf(mB, mxB);
        float cA = ex2(mA - mnA), cB = ex2(mB - mnB);
        mA = mnA; mB = mnB;
        float sumA = 0.0f, sumB = 0.0f;
#pragma unroll
        for (int nt = 0; nt < 8; nt++) {
            s[nt][0] = ex2(s[nt][0] - mnA);
            s[nt][1] = ex2(s[nt][1] - mnA);
            s[nt][2] = ex2(s[nt][2] - mnB);
            s[nt][3] = ex2(s[nt][3] - mnB);
            sumA += s[nt][0] + s[nt][1];
            sumB += s[nt][2] + s[nt][3];
        }
        sumA += __shfl_xor_sync(0xffffffffu, sumA, 1);
        sumA += __shfl_xor_sync(0xffffffffu, sumA, 2);
        sumB += __shfl_xor_sync(0xffffffffu, sumB, 1);
        sumB += __shfl_xor_sync(0xffffffffu, sumB, 2);
        lA = lA * cA + sumA;
        lB = lB * cB + sumB;

#pragma unroll
        for (int nt = 0; nt < 8; nt++) {
            o[nt][0] *= cA; o[nt][1] *= cA;
            o[nt][2] *= cB; o[nt][3] *= cB;
        }
        const unsigned vb = vb0 + st * (STAGE_H * 2);
#pragma unroll
        for (int ks = 0; ks < 4; ks++) {
            unsigned pa[4];
            pa[0] = h2u(s[2 * ks][0], s[2 * ks][1]);
            pa[1] = h2u(s[2 * ks][2], s[2 * ks][3]);
            pa[2] = h2u(s[2 * ks + 1][0], s[2 * ks + 1][1]);
            pa[3] = h2u(s[2 * ks + 1][2], s[2 * ks + 1][3]);
#pragma unroll
            for (int j = 0; j < 4; j++) {
                unsigned vfr[4];
                ldsm4t(vfr[0], vfr[1], vfr[2], vfr[3], vb + ks * (16 * KST * 2) + j * 32);
                mma16(o[2 * j], pa, vfr[0], vfr[1]);
                mma16(o[2 * j + 1], pa, vfr[2], vfr[3]);
            }
        }
        st = (st == 2) ? 0 : st + 1;
        st2 = (st2 == 2) ? 0 : st2 + 1;
    }

    __syncthreads();
    {
        float rA = 1.0f / lA, rB = 1.0f / lB;
#pragma unroll
        for (int nt = 0; nt < 8; nt++) {
            *(float2*)&So[(qw + g) * OST + 8 * nt + 2 * tig] =
                make_float2(o[nt][0] * rA, o[nt][1] * rA);
            *(float2*)&So[(qw + g + 8) * OST + 8 * nt + 2 * tig] =
                make_float2(o[nt][2] * rB, o[nt][3] * rB);
        }
    }
    __syncthreads();

    // scattered scrambled reshape + residual:
    //   out[b, 128h + 2d + (q>=1024), q % 1024] = O[i][d] + queries[...]
    const int dd = tid >> 2;  // d: 0..63
    const int c = tid & 3;
#pragma unroll 8
    for (int t = 0; t < 32; t++) {
        const int i = 4 * t + c;
        const int q = sidx[i];
        if (q >= 0) {
            const int srow = 128 * h + 2 * dd + (q >> 10);
            const size_t off = (size_t)(b * 2048 + srow) * 1024 + (q & 1023);
            out[off] = So[i * OST + dd] + queries[off];
        }
    }
}

// ---------------- launch ----------------
extern "C" void kernel_launch(void* const* d_in, const int* in_sizes, int n_in, void* d_out,
                              int out_size) {
    const float* queries = (const float*)d_in[0];
    const float* keys = (const float*)d_in[1];
    const float* values = (const float*)d_in[2];
    const int* amask = (const int*)d_in[3];
    const float* Wq = (const float*)d_in[4];
    const float* bq = (const float*)d_in[5];
    const float* Wk = (const float*)d_in[6];
    const float* bk = (const float*)d_in[7];
    const float* Wv = (const float*)d_in[8];
    const float* bv = (const float*)d_in[9];
    float* out = (float*)d_out;

    compact_kernel<<<BB, 32>>>(amask);

    dim3 gc(512, 6, 1);
    cvt_kernel<<<gc, 256>>>(queries, keys, values, Wq, Wk, Wv);

    cudaFuncSetAttribute(qkv_gemm, cudaFuncAttributeMaxDynamicSharedMemorySize, GEMM_SMEM);
    dim3 g1(8, 32, 3);
    qkv_gemm<<<g1, 256, GEMM_SMEM>>>(bq, bk, bv);

    vmean_kernel<<<dim3(16, BB), 256>>>(queries, out);

    cudaFuncSetAttribute(attn_mma, cudaFuncAttributeMaxDynamicSharedMemorySize, ATTN_SMEM);
    dim3 g2(16, 16, BB);
    attn_mma<<<g2, 256, ATTN_SMEM>>>(queries, out);
}

// round 10
// speedup vs baseline: 1.5451x; 1.5451x over previous
#include <cuda_runtime.h>
#include <cuda_fp16.h>

// Problem constants
#define BB 2
#define SS 2048
#define DD 1024

// fp16 staging buffers + compaction lists (device globals: no allocation)
__device__ __half g_Q[BB * SS * DD];   // compacted unmasked Q rows
__device__ __half g_K[BB * SS * DD];
__device__ __half g_V[BB * SS * DD];
__device__ __half g_Xh[3][BB * SS * DD];
__device__ __half g_Wh[3][DD * DD];
__device__ int g_qidx[BB][SS];  // unmasked query indices (ascending)
__device__ int g_midx[BB][SS];  // masked query indices
__device__ int g_ncnt[BB];      // # unmasked
__device__ int g_mcnt[BB];      // # masked
__device__ float g_vpart[BB][16][16][64];  // partial V sums per (b,h,chunk,d)

// ---------- helpers ----------
__device__ __forceinline__ unsigned sptr(const void* p) {
    return (unsigned)__cvta_generic_to_shared(p);
}
__device__ __forceinline__ void ldsm4(unsigned& r0, unsigned& r1, unsigned& r2, unsigned& r3,
                                      unsigned addr) {
    asm volatile("ldmatrix.sync.aligned.m8n8.x4.shared.b16 {%0,%1,%2,%3}, [%4];"
                 : "=r"(r0), "=r"(r1), "=r"(r2), "=r"(r3)
                 : "r"(addr));
}
__device__ __forceinline__ void ldsm4t(unsigned& r0, unsigned& r1, unsigned& r2, unsigned& r3,
                                       unsigned addr) {
    asm volatile("ldmatrix.sync.aligned.m8n8.x4.trans.shared.b16 {%0,%1,%2,%3}, [%4];"
                 : "=r"(r0), "=r"(r1), "=r"(r2), "=r"(r3)
                 : "r"(addr));
}
__device__ __forceinline__ void mma16(float c[4], const unsigned a[4], unsigned b0, unsigned b1) {
    asm volatile(
        "mma.sync.aligned.m16n8k16.row.col.f32.f16.f16.f32 "
        "{%0,%1,%2,%3},{%4,%5,%6,%7},{%8,%9},{%0,%1,%2,%3};"
        : "+f"(c[0]), "+f"(c[1]), "+f"(c[2]), "+f"(c[3])
        : "r"(a[0]), "r"(a[1]), "r"(a[2]), "r"(a[3]), "r"(b0), "r"(b1));
}
__device__ __forceinline__ void cpa16(unsigned s, const void* g) {
    asm volatile("cp.async.cg.shared.global [%0], [%1], 16;" ::"r"(s), "l"(g));
}
__device__ __forceinline__ unsigned h2u(float a, float b) {
    __half2 h = __floats2half2_rn(a, b);
    return *(unsigned*)&h;
}
__device__ __forceinline__ float ex2(float x) {
    float y;
    asm("ex2.approx.ftz.f32 %0, %1;" : "=f"(y) : "f"(x));
    return y;
}

// =====================================================================
// Mask compaction: one warp per batch, ballot-based stable partition.
// =====================================================================
__global__ void compact_kernel(const int* __restrict__ amask) {
    const int b = blockIdx.x;
    const int lane = threadIdx.x;
    int nu = 0, nm = 0;
    for (int i0 = 0; i0 < SS; i0 += 32) {
        int m = amask[b * SS + i0 + lane] != 0;
        unsigned bal = __ballot_sync(0xffffffffu, m);
        unsigned below = (1u << lane) - 1u;
        if (m)
            g_qidx[b][nu + __popc(bal & below)] = i0 + lane;
        else
            g_midx[b][nm + __popc(~bal & below)] = i0 + lane;
        nu += __popc(bal);
        nm += 32 - __popc(bal);
    }
    if (lane == 0) { g_ncnt[b] = nu; g_mcnt[b] = nm; }
}

// =====================================================================
// fp32 -> fp16 conversion pass (bandwidth-bound)
// =====================================================================
__global__ void __launch_bounds__(256) cvt_kernel(
    const float* __restrict__ q, const float* __restrict__ k, const float* __restrict__ v,
    const float* __restrict__ wq, const float* __restrict__ wk, const float* __restrict__ wv) {
    const int sel = blockIdx.y;
    const float* src;
    __half* dst;
    int n4;
    switch (sel) {
        case 0: src = q;  dst = g_Xh[0]; n4 = BB * SS * DD / 4; break;
        case 1: src = k;  dst = g_Xh[1]; n4 = BB * SS * DD / 4; break;
        case 2: src = v;  dst = g_Xh[2]; n4 = BB * SS * DD / 4; break;
        case 3: src = wq; dst = g_Wh[0]; n4 = DD * DD / 4; break;
        case 4: src = wk; dst = g_Wh[1]; n4 = DD * DD / 4; break;
        default: src = wv; dst = g_Wh[2]; n4 = DD * DD / 4; break;
    }
    const int stride = gridDim.x * blockDim.x;
    for (int i = blockIdx.x * blockDim.x + threadIdx.x; i < n4; i += stride) {
        float4 f = ((const float4*)src)[i];
        __half2 h0 = __floats2half2_rn(f.x, f.y);
        __half2 h1 = __floats2half2_rn(f.z, f.w);
        uint2 o;
        o.x = *(unsigned*)&h0;
        o.y = *(unsigned*)&h1;
        ((uint2*)dst)[i] = o;
    }
}

// =====================================================================
// QKV projection (fp16): out = relu(X @ W^T + b). z=0 (Q) processes only
// unmasked rows (gathered input, compacted output). 3-stage cp.async.
// =====================================================================
#define QST 72
#define QSTG (128 * QST)
#define GEMM_SMEM (6 * QSTG * 2)

__global__ void __launch_bounds__(256, 2) qkv_gemm(
    const float* __restrict__ bq, const float* __restrict__ bk, const float* __restrict__ bv) {
    const int z = blockIdx.z;
    const __half* X = g_Xh[z];
    const __half* W = g_Wh[z];
    const float* bias = (z == 0) ? bq : (z == 1) ? bk : bv;
    __half* out = (z == 0) ? g_Q : (z == 1) ? g_K : g_V;

    const int tid = threadIdx.x;
    const int my = blockIdx.y;
    const int crow = tid >> 1;        // loader row within tile
    const int ccol = (tid & 1) * 32;  // loader col (halves)

    int obase, grow;
    if (z == 0) {
        const int bqb = my >> 4, tq = my & 15;
        const int nu = g_ncnt[bqb];
        if (tq * 128 >= nu) return;  // inactive tile (whole block exits)
        obase = bqb * 2048 + tq * 128;
        int i = tq * 128 + crow;
        if (i >= nu) i = nu - 1;  // clamp: duplicate last row (finite, discarded)
        grow = bqb * 2048 + g_qidx[bqb][i];
    } else {
        obase = my * 128;
        grow = my * 128 + crow;
    }

    extern __shared__ __align__(16) char smraw[];
    __half* XB = (__half*)smraw;
    __half* WB = (__half*)smraw + 3 * QSTG;

    const int warp = tid >> 5, lane = tid & 31;
    const int g = lane >> 2, tig = lane & 3;
    const int m0 = (warp >> 1) * 32;
    const int n0 = (warp & 1) * 64;
    const int bn = blockIdx.x * 128;

    const unsigned xdst = sptr(&XB[crow * QST + ccol]);
    const unsigned wdst = sptr(&WB[crow * QST + ccol]);
    const size_t xrow = (size_t)grow * 1024 + ccol;
    const size_t wrow = (size_t)(bn + crow) * 1024 + ccol;

    float acc[2][8][4];
#pragma unroll
    for (int mt = 0; mt < 2; mt++)
#pragma unroll
        for (int nt = 0; nt < 8; nt++)
#pragma unroll
            for (int i = 0; i < 4; i++) acc[mt][nt][i] = 0.0f;

    const unsigned xa0 = sptr(&XB[(m0 + (lane & 15)) * QST + (lane >> 4) * 8]);
    const unsigned xa1 = sptr(&XB[(m0 + 16 + (lane & 15)) * QST + (lane >> 4) * 8]);
    const unsigned wbb = sptr(&WB[(n0 + 8 * (lane >> 4) + (lane & 7)) * QST + ((lane >> 3) & 1) * 8]);

#pragma unroll
    for (int p = 0; p < 2; p++) {
        const unsigned soff = p * (QSTG * 2);
        const int k0 = p * 64;
#pragma unroll
        for (int c = 0; c < 4; c++) {
            cpa16(xdst + soff + c * 16, X + xrow + k0 + c * 8);
            cpa16(wdst + soff + c * 16, W + wrow + k0 + c * 8);
        }
        asm volatile("cp.async.commit_group;");
    }

    int st = 0, st2 = 2;
    for (int it = 0; it < 16; it++) {
        asm volatile("cp.async.wait_group 1;" ::: "memory");
        __syncthreads();

        if (it + 2 < 16) {
            const int k0 = (it + 2) * 64;
            const unsigned soff = st2 * (QSTG * 2);
#pragma unroll
            for (int c = 0; c < 4; c++) {
                cpa16(xdst + soff + c * 16, X + xrow + k0 + c * 8);
                cpa16(wdst + soff + c * 16, W + wrow + k0 + c * 8);
            }
        }
        asm volatile("cp.async.commit_group;");

        const unsigned sa = st * (QSTG * 2);
#pragma unroll
        for (int ks = 0; ks < 4; ks++) {
            unsigned a0[4], a1[4];
            ldsm4(a0[0], a0[1], a0[2], a0[3], xa0 + sa + ks * 32);
            ldsm4(a1[0], a1[1], a1[2], a1[3], xa1 + sa + ks * 32);
#pragma unroll
            for (int j = 0; j < 4; j++) {
                unsigned b[4];
                ldsm4(b[0], b[1], b[2], b[3], wbb + sa + j * (16 * QST * 2) + ks * 32);
                mma16(acc[0][2 * j], a0, b[0], b[1]);
                mma16(acc[0][2 * j + 1], a0, b[2], b[3]);
                mma16(acc[1][2 * j], a1, b[0], b[1]);
                mma16(acc[1][2 * j + 1], a1, b[2], b[3]);
            }
        }
        st = (st == 2) ? 0 : st + 1;
        st2 = (st2 == 2) ? 0 : st2 + 1;
    }

#pragma unroll
    for (int nt = 0; nt < 8; nt++) {
        int n = bn + n0 + 8 * nt + 2 * tig;
        float b0 = __ldg(&bias[n]), b1 = __ldg(&bias[n + 1]);
#pragma unroll
        for (int mt = 0; mt < 2; mt++) {
            int m = obase + m0 + 16 * mt + g;
            float v0 = acc[mt][nt][0] + b0, v1 = acc[mt][nt][1] + b1;
            v0 = v0 > 0.f ? v0 : 0.f;
            v1 = v1 > 0.f ? v1 : 0.f;
            *(__half2*)&out[(size_t)m * 1024 + n] = __floats2half2_rn(v0, v1);
            float v2 = acc[mt][nt][2] + b0, v3 = acc[mt][nt][3] + b1;
            v2 = v2 > 0.f ? v2 : 0.f;
            v3 = v3 > 0.f ? v3 : 0.f;
            *(__half2*)&out[(size_t)(m + 8) * 1024 + n] = __floats2half2_rn(v2, v3);
        }
    }
}

// =====================================================================
// V-mean phase 1: partial sums. grid (16h, BB, 16 chunks), 256 thr.
// Each block reduces 128 rows x 64 dims (coalesced) into g_vpart.
// =====================================================================
__global__ void __launch_bounds__(256) vpart_kernel() {
    __shared__ float part[4][64];
    const int h = blockIdx.x, b = blockIdx.y, chn = blockIdx.z;
    const int d = threadIdx.x & 63, r0 = threadIdx.x >> 6;

    float sum = 0.0f;
    const __half* vp = g_V + (size_t)(b * 2048 + chn * 128 + r0) * 1024 + h * 64 + d;
#pragma unroll 8
    for (int k = 0; k < 32; k++) sum += __half2float(vp[(size_t)(4 * k) * 1024]);
    part[r0][d] = sum;
    __syncthreads();
    if (r0 == 0)
        g_vpart[b][h][chn][d] = part[0][d] + part[1][d] + part[2][d] + part[3][d];
}

// =====================================================================
// V-mean phase 2: masked rows get out = mean(V) + residual.
// grid (16h, BB, 8 slices), 256 thr (4 row-groups x 64 dims).
// =====================================================================
__global__ void __launch_bounds__(256) vscatter_kernel(const float* __restrict__ queries,
                                                       float* __restrict__ out) {
    __shared__ float mean[64];
    const int h = blockIdx.x, b = blockIdx.y, sl = blockIdx.z;
    const int d = threadIdx.x & 63, ch = threadIdx.x >> 6;

    if (ch == 0) {
        float s = 0.0f;
#pragma unroll
        for (int c = 0; c < 16; c++) s += g_vpart[b][h][c][d];
        mean[d] = s * (1.0f / 2048.0f);
    }
    __syncthreads();
    const float mv = mean[d];

    const int nm = g_mcnt[b];
    for (int j = ch + 4 * sl; j < nm; j += 32) {
        const int q = g_midx[b][j];
        const int srow = 128 * h + 2 * d + (q >> 10);
        const size_t off = (size_t)(b * 2048 + srow) * 1024 + (q & 1023);
        out[off] = mv + queries[off];
    }
}

// =====================================================================
// Flash attention over COMPACTED unmasked queries (no mask term), with
// scattered scrambled-reshape epilogue + residual.
// =====================================================================
#define KST 72
#define OST 68
#define STAGE_H (64 * KST)
#define ATTN_SMEM ((6 * STAGE_H + 128 * KST) * 2)

__global__ void __launch_bounds__(256) attn_mma(const float* __restrict__ queries,
                                                float* __restrict__ out) {
    const int b = blockIdx.z, h = blockIdx.y;
    const int q0 = blockIdx.x * 128;
    const int nu = g_ncnt[b];
    if (q0 >= nu) return;  // inactive tile

    extern __shared__ __align__(16) char smbase[];
    __half* KB = (__half*)smbase;
    __half* VB = (__half*)smbase + 3 * STAGE_H;
    __half* Qs = (__half*)smbase + 6 * STAGE_H;
    float* So = (float*)smbase;
    __shared__ int sidx[128];

    const int tid = threadIdx.x;
    const int warp = tid >> 5, lane = tid & 31;
    const int g = lane >> 2, tig = lane & 3;
    const int qw = warp * 16;

    if (tid < 128) sidx[tid] = (q0 + tid < nu) ? g_qidx[b][q0 + tid] : -1;

    const int crow = tid >> 2;
    const int ccol = (tid & 3) * 16;
    const unsigned kdst = sptr(&KB[crow * KST + ccol]);
    const unsigned vdst = sptr(&VB[crow * KST + ccol]);

#pragma unroll
    for (int p = 0; p < 2; p++) {
        const size_t gofs = (size_t)(b * 2048 + p * 64 + crow) * 1024 + h * 64 + ccol;
        const unsigned soff = p * (STAGE_H * 2);
        cpa16(kdst + soff, g_K + gofs);
        cpa16(kdst + soff + 16, g_K + gofs + 8);
        cpa16(vdst + soff, g_V + gofs);
        cpa16(vdst + soff + 16, g_V + gofs + 8);
        asm volatile("cp.async.commit_group;");
    }

    // stage Q (compacted rows; scaled by 0.125*log2e), frags to registers
    {
        int row = tid >> 1;
        int koff = (tid & 1) * 32;
        const __half* qsrc = g_Q + (size_t)(b * 2048 + q0 + row) * 1024 + h * 64 + koff;
        const float qs = 0.125f * 1.4426950408889634f;
        const __half2 sc = __floats2half2_rn(qs, qs);
        __half2 v[16];
        *(uint4*)&v[0] = *(const uint4*)&qsrc[0];
        *(uint4*)&v[4] = *(const uint4*)&qsrc[8];
        *(uint4*)&v[8] = *(const uint4*)&qsrc[16];
        *(uint4*)&v[12] = *(const uint4*)&qsrc[24];
#pragma unroll
        for (int j = 0; j < 16; j++) v[j] = __hmul2(v[j], sc);
        *(uint4*)&Qs[row * KST + koff] = *(uint4*)&v[0];
        *(uint4*)&Qs[row * KST + koff + 8] = *(uint4*)&v[4];
        *(uint4*)&Qs[row * KST + koff + 16] = *(uint4*)&v[8];
        *(uint4*)&Qs[row * KST + koff + 24] = *(uint4*)&v[12];
    }
    __syncwarp();
    unsigned qf[4][4];
    {
        unsigned qa = sptr(&Qs[(qw + (lane & 15)) * KST + (lane >> 4) * 8]);
#pragma unroll
        for (int ks = 0; ks < 4; ks++)
            ldsm4(qf[ks][0], qf[ks][1], qf[ks][2], qf[ks][3], qa + ks * 32);
    }

    float mA = -1e30f, mB = -1e30f, lA = 0.0f, lB = 0.0f;
    float o[8][4];
#pragma unroll
    for (int nt = 0; nt < 8; nt++)
#pragma unroll
        for (int i = 0; i < 4; i++) o[nt][i] = 0.0f;

    const unsigned kb0 = sptr(&KB[(8 * (lane >> 4) + (lane & 7)) * KST + ((lane >> 3) & 1) * 8]);
    const unsigned vb0 = sptr(&VB[(8 * ((lane >> 3) & 1) + (lane & 7)) * KST + (lane >> 4) * 8]);

    int st = 0, st2 = 2;
    for (int jt = 0; jt < 32; jt++) {
        asm volatile("cp.async.wait_group 1;" ::: "memory");
        __syncthreads();

        if (jt + 2 < 32) {
            const size_t gofs = (size_t)(b * 2048 + (jt + 2) * 64 + crow) * 1024 + h * 64 + ccol;
            const unsigned soff = st2 * (STAGE_H * 2);
            cpa16(kdst + soff, g_K + gofs);
            cpa16(kdst + soff + 16, g_K + gofs + 8);
            cpa16(vdst + soff, g_V + gofs);
            cpa16(vdst + soff + 16, g_V + gofs + 8);
        }
        asm volatile("cp.async.commit_group;");

        const unsigned kb = kb0 + st * (STAGE_H * 2);
        float s[8][4];
#pragma unroll
        for (int nt = 0; nt < 8; nt++)
#pragma unroll
            for (int i = 0; i < 4; i++) s[nt][i] = 0.0f;
#pragma unroll
        for (int ks = 0; ks < 4; ks++) {
#pragma unroll
            for (int j = 0; j < 4; j++) {
                unsigned bfr[4];
                ldsm4(bfr[0], bfr[1], bfr[2], bfr[3], kb + j * (16 * KST * 2) + ks * 32);
                mma16(s[2 * j], qf[ks], bfr[0], bfr[1]);
                mma16(s[2 * j + 1], qf[ks], bfr[2], bfr[3]);
            }
        }

        float mxA = s[0][0], mxB = s[0][2];
#pragma unroll
        for (int nt = 0; nt < 8; nt++) {
            mxA = fmaxf(mxA, fmaxf(s[nt][0], s[nt][1]));
            mxB = fmaxf(mxB, fmaxf(s[nt][2], s[nt][3]));
        }
        mxA = fmaxf(mxA, __shfl_xor_sync(0xffffffffu, mxA, 1));
        mxA = fmaxf(mxA, __shfl_xor_sync(0xffffffffu, mxA, 2));
        mxB = fmaxf(mxB, __shfl_xor_sync(0xffffffffu, mxB, 1));
        mxB = fmaxf(mxB, __shfl_xor_sync(0xffffffffu, mxB, 2));
        float mnA = fmaxf(mA, mxA), mnB = fmaxf(mB, mxB);
        float cA = ex2(mA - mnA), cB = ex2(mB - mnB);
        mA = mnA; mB = mnB;
        float sumA = 0.0f, sumB = 0.0f;
#pragma unroll
        for (int nt = 0; nt < 8; nt++) {
            s[nt][0] = ex2(s[nt][0] - mnA);
            s[nt][1] = ex2(s[nt][1] - mnA);
            s[nt][2] = ex2(s[nt][2] - mnB);
            s[nt][3] = ex2(s[nt][3] - mnB);
            sumA += s[nt][0] + s[nt][1];
            sumB += s[nt][2] + s[nt][3];
        }
        sumA += __shfl_xor_sync(0xffffffffu, sumA, 1);
        sumA += __shfl_xor_sync(0xffffffffu, sumA, 2);
        sumB += __shfl_xor_sync(0xffffffffu, sumB, 1);
        sumB += __shfl_xor_sync(0xffffffffu, sumB, 2);
        lA = lA * cA + sumA;
        lB = lB * cB + sumB;

#pragma unroll
        for (int nt = 0; nt < 8; nt++) {
            o[nt][0] *= cA; o[nt][1] *= cA;
            o[nt][2] *= cB; o[nt][3] *= cB;
        }
        const unsigned vb = vb0 + st * (STAGE_H * 2);
#pragma unroll
        for (int ks = 0; ks < 4; ks++) {
            unsigned pa[4];
            pa[0] = h2u(s[2 * ks][0], s[2 * ks][1]);
            pa[1] = h2u(s[2 * ks][2], s[2 * ks][3]);
            pa[2] = h2u(s[2 * ks + 1][0], s[2 * ks + 1][1]);
            pa[3] = h2u(s[2 * ks + 1][2], s[2 * ks + 1][3]);
#pragma unroll
            for (int j = 0; j < 4; j++) {
                unsigned vfr[4];
                ldsm4t(vfr[0], vfr[1], vfr[2], vfr[3], vb + ks * (16 * KST * 2) + j * 32);
                mma16(o[2 * j], pa, vfr[0], vfr[1]);
                mma16(o[2 * j + 1], pa, vfr[2], vfr[3]);
            }
        }
        st = (st == 2) ? 0 : st + 1;
        st2 = (st2 == 2) ? 0 : st2 + 1;
    }

    __syncthreads();
    {
        float rA = 1.0f / lA, rB = 1.0f / lB;
#pragma unroll
        for (int nt = 0; nt < 8; nt++) {
            *(float2*)&So[(qw + g) * OST + 8 * nt + 2 * tig] =
                make_float2(o[nt][0] * rA, o[nt][1] * rA);
            *(float2*)&So[(qw + g + 8) * OST + 8 * nt + 2 * tig] =
                make_float2(o[nt][2] * rB, o[nt][3] * rB);
        }
    }
    __syncthreads();

    // scattered scrambled reshape + residual:
    //   out[b, 128h + 2d + (q>=1024), q % 1024] = O[i][d] + queries[...]
    const int dd = tid >> 2;  // d: 0..63
    const int c = tid & 3;
#pragma unroll 8
    for (int t = 0; t < 32; t++) {
        const int i = 4 * t + c;
        const int q = sidx[i];
        if (q >= 0) {
            const int srow = 128 * h + 2 * dd + (q >> 10);
            const size_t off = (size_t)(b * 2048 + srow) * 1024 + (q & 1023);
            out[off] = So[i * OST + dd] + queries[off];
        }
    }
}

// ---------------- launch ----------------
extern "C" void kernel_launch(void* const* d_in, const int* in_sizes, int n_in, void* d_out,
                              int out_size) {
    const float* queries = (const float*)d_in[0];
    const float* keys = (const float*)d_in[1];
    const float* values = (const float*)d_in[2];
    const int* amask = (const int*)d_in[3];
    const float* Wq = (const float*)d_in[4];
    const float* bq = (const float*)d_in[5];
    const float* Wk = (const float*)d_in[6];
    const float* bk = (const float*)d_in[7];
    const float* Wv = (const float*)d_in[8];
    const float* bv = (const float*)d_in[9];
    float* out = (float*)d_out;

    compact_kernel<<<BB, 32>>>(amask);

    dim3 gc(512, 6, 1);
    cvt_kernel<<<gc, 256>>>(queries, keys, values, Wq, Wk, Wv);

    cudaFuncSetAttribute(qkv_gemm, cudaFuncAttributeMaxDynamicSharedMemorySize, GEMM_SMEM);
    dim3 g1(8, 32, 3);
    qkv_gemm<<<g1, 256, GEMM_SMEM>>>(bq, bk, bv);

    vpart_kernel<<<dim3(16, BB, 16), 256>>>();
    vscatter_kernel<<<dim3(16, BB, 8), 256>>>(queries, out);

    cudaFuncSetAttribute(attn_mma, cudaFuncAttributeMaxDynamicSharedMemorySize, ATTN_SMEM);
    dim3 g2(16, 16, BB);
    attn_mma<<<g2, 256, ATTN_SMEM>>>(queries, out);
}

// round 11
// speedup vs baseline: 1.7727x; 1.1473x over previous
#include <cuda_runtime.h>
#include <cuda_fp16.h>

// Problem constants
#define BB 2
#define SS 2048
#define DD 1024

// fp16 staging buffers + compaction lists (device globals: no allocation)
__device__ __half g_Q[BB * SS * DD];   // compacted unmasked Q rows
__device__ __half g_K[BB * SS * DD];
__device__ __half g_V[BB * SS * DD];
__device__ __half g_Xh[3][BB * SS * DD];
__device__ __half g_Wh[3][DD * DD];
__device__ int g_qidx[BB][SS];  // unmasked query indices (ascending)
__device__ int g_ncnt[BB];      // # unmasked
__device__ float g_vpart[BB][16][16][64];  // partial V sums per (b,h,chunk,d)

// ---------- helpers ----------
__device__ __forceinline__ unsigned sptr(const void* p) {
    return (unsigned)__cvta_generic_to_shared(p);
}
__device__ __forceinline__ void ldsm4(unsigned& r0, unsigned& r1, unsigned& r2, unsigned& r3,
                                      unsigned addr) {
    asm volatile("ldmatrix.sync.aligned.m8n8.x4.shared.b16 {%0,%1,%2,%3}, [%4];"
                 : "=r"(r0), "=r"(r1), "=r"(r2), "=r"(r3)
                 : "r"(addr));
}
__device__ __forceinline__ void ldsm4t(unsigned& r0, unsigned& r1, unsigned& r2, unsigned& r3,
                                       unsigned addr) {
    asm volatile("ldmatrix.sync.aligned.m8n8.x4.trans.shared.b16 {%0,%1,%2,%3}, [%4];"
                 : "=r"(r0), "=r"(r1), "=r"(r2), "=r"(r3)
                 : "r"(addr));
}
__device__ __forceinline__ void mma16(float c[4], const unsigned a[4], unsigned b0, unsigned b1) {
    asm volatile(
        "mma.sync.aligned.m16n8k16.row.col.f32.f16.f16.f32 "
        "{%0,%1,%2,%3},{%4,%5,%6,%7},{%8,%9},{%0,%1,%2,%3};"
        : "+f"(c[0]), "+f"(c[1]), "+f"(c[2]), "+f"(c[3])
        : "r"(a[0]), "r"(a[1]), "r"(a[2]), "r"(a[3]), "r"(b0), "r"(b1));
}
__device__ __forceinline__ void cpa16(unsigned s, const void* g) {
    asm volatile("cp.async.cg.shared.global [%0], [%1], 16;" ::"r"(s), "l"(g));
}
__device__ __forceinline__ unsigned h2u(float a, float b) {
    __half2 h = __floats2half2_rn(a, b);
    return *(unsigned*)&h;
}
__device__ __forceinline__ float ex2(float x) {
    float y;
    asm("ex2.approx.ftz.f32 %0, %1;" : "=f"(y) : "f"(x));
    return y;
}

// =====================================================================
// Mask compaction: one warp per batch, ballot-based stable partition.
// =====================================================================
__global__ void compact_kernel(const int* __restrict__ amask) {
    const int b = blockIdx.x;
    const int lane = threadIdx.x;
    int nu = 0;
    for (int i0 = 0; i0 < SS; i0 += 32) {
        int m = amask[b * SS + i0 + lane] != 0;
        unsigned bal = __ballot_sync(0xffffffffu, m);
        unsigned below = (1u << lane) - 1u;
        if (m) g_qidx[b][nu + __popc(bal & below)] = i0 + lane;
        nu += __popc(bal);
    }
    if (lane == 0) g_ncnt[b] = nu;
}

// =====================================================================
// fp32 -> fp16 conversion pass (bandwidth-bound)
// =====================================================================
__global__ void __launch_bounds__(256) cvt_kernel(
    const float* __restrict__ q, const float* __restrict__ k, const float* __restrict__ v,
    const float* __restrict__ wq, const float* __restrict__ wk, const float* __restrict__ wv) {
    const int sel = blockIdx.y;
    const float* src;
    __half* dst;
    int n4;
    switch (sel) {
        case 0: src = q;  dst = g_Xh[0]; n4 = BB * SS * DD / 4; break;
        case 1: src = k;  dst = g_Xh[1]; n4 = BB * SS * DD / 4; break;
        case 2: src = v;  dst = g_Xh[2]; n4 = BB * SS * DD / 4; break;
        case 3: src = wq; dst = g_Wh[0]; n4 = DD * DD / 4; break;
        case 4: src = wk; dst = g_Wh[1]; n4 = DD * DD / 4; break;
        default: src = wv; dst = g_Wh[2]; n4 = DD * DD / 4; break;
    }
    const int stride = gridDim.x * blockDim.x;
    for (int i = blockIdx.x * blockDim.x + threadIdx.x; i < n4; i += stride) {
        float4 f = ((const float4*)src)[i];
        __half2 h0 = __floats2half2_rn(f.x, f.y);
        __half2 h1 = __floats2half2_rn(f.z, f.w);
        uint2 o;
        o.x = *(unsigned*)&h0;
        o.y = *(unsigned*)&h1;
        ((uint2*)dst)[i] = o;
    }
}

// =====================================================================
// QKV projection (fp16): out = relu(X @ W^T + b). z=0 (Q) processes only
// unmasked rows (gathered input, compacted output). 3-stage cp.async.
// =====================================================================
#define QST 72
#define QSTG (128 * QST)
#define GEMM_SMEM (6 * QSTG * 2)

__global__ void __launch_bounds__(256, 2) qkv_gemm(
    const float* __restrict__ bq, const float* __restrict__ bk, const float* __restrict__ bv) {
    const int z = blockIdx.z;
    const __half* X = g_Xh[z];
    const __half* W = g_Wh[z];
    const float* bias = (z == 0) ? bq : (z == 1) ? bk : bv;
    __half* out = (z == 0) ? g_Q : (z == 1) ? g_K : g_V;

    const int tid = threadIdx.x;
    const int my = blockIdx.y;
    const int crow = tid >> 1;        // loader row within tile
    const int ccol = (tid & 1) * 32;  // loader col (halves)

    int obase, grow;
    if (z == 0) {
        const int bqb = my >> 4, tq = my & 15;
        const int nu = g_ncnt[bqb];
        if (tq * 128 >= nu) return;  // inactive tile (whole block exits)
        obase = bqb * 2048 + tq * 128;
        int i = tq * 128 + crow;
        if (i >= nu) i = nu - 1;  // clamp: duplicate last row (finite, discarded)
        grow = bqb * 2048 + g_qidx[bqb][i];
    } else {
        obase = my * 128;
        grow = my * 128 + crow;
    }

    extern __shared__ __align__(16) char smraw[];
    __half* XB = (__half*)smraw;
    __half* WB = (__half*)smraw + 3 * QSTG;

    const int warp = tid >> 5, lane = tid & 31;
    const int g = lane >> 2, tig = lane & 3;
    const int m0 = (warp >> 1) * 32;
    const int n0 = (warp & 1) * 64;
    const int bn = blockIdx.x * 128;

    const unsigned xdst = sptr(&XB[crow * QST + ccol]);
    const unsigned wdst = sptr(&WB[crow * QST + ccol]);
    const size_t xrow = (size_t)grow * 1024 + ccol;
    const size_t wrow = (size_t)(bn + crow) * 1024 + ccol;

    float acc[2][8][4];
#pragma unroll
    for (int mt = 0; mt < 2; mt++)
#pragma unroll
        for (int nt = 0; nt < 8; nt++)
#pragma unroll
            for (int i = 0; i < 4; i++) acc[mt][nt][i] = 0.0f;

    const unsigned xa0 = sptr(&XB[(m0 + (lane & 15)) * QST + (lane >> 4) * 8]);
    const unsigned xa1 = sptr(&XB[(m0 + 16 + (lane & 15)) * QST + (lane >> 4) * 8]);
    const unsigned wbb = sptr(&WB[(n0 + 8 * (lane >> 4) + (lane & 7)) * QST + ((lane >> 3) & 1) * 8]);

#pragma unroll
    for (int p = 0; p < 2; p++) {
        const unsigned soff = p * (QSTG * 2);
        const int k0 = p * 64;
#pragma unroll
        for (int c = 0; c < 4; c++) {
            cpa16(xdst + soff + c * 16, X + xrow + k0 + c * 8);
            cpa16(wdst + soff + c * 16, W + wrow + k0 + c * 8);
        }
        asm volatile("cp.async.commit_group;");
    }

    int st = 0, st2 = 2;
    for (int it = 0; it < 16; it++) {
        asm volatile("cp.async.wait_group 1;" ::: "memory");
        __syncthreads();

        if (it + 2 < 16) {
            const int k0 = (it + 2) * 64;
            const unsigned soff = st2 * (QSTG * 2);
#pragma unroll
            for (int c = 0; c < 4; c++) {
                cpa16(xdst + soff + c * 16, X + xrow + k0 + c * 8);
                cpa16(wdst + soff + c * 16, W + wrow + k0 + c * 8);
            }
        }
        asm volatile("cp.async.commit_group;");

        const unsigned sa = st * (QSTG * 2);
#pragma unroll
        for (int ks = 0; ks < 4; ks++) {
            unsigned a0[4], a1[4];
            ldsm4(a0[0], a0[1], a0[2], a0[3], xa0 + sa + ks * 32);
            ldsm4(a1[0], a1[1], a1[2], a1[3], xa1 + sa + ks * 32);
#pragma unroll
            for (int j = 0; j < 4; j++) {
                unsigned b[4];
                ldsm4(b[0], b[1], b[2], b[3], wbb + sa + j * (16 * QST * 2) + ks * 32);
                mma16(acc[0][2 * j], a0, b[0], b[1]);
                mma16(acc[0][2 * j + 1], a0, b[2], b[3]);
                mma16(acc[1][2 * j], a1, b[0], b[1]);
                mma16(acc[1][2 * j + 1], a1, b[2], b[3]);
            }
        }
        st = (st == 2) ? 0 : st + 1;
        st2 = (st2 == 2) ? 0 : st2 + 1;
    }

#pragma unroll
    for (int nt = 0; nt < 8; nt++) {
        int n = bn + n0 + 8 * nt + 2 * tig;
        float b0 = __ldg(&bias[n]), b1 = __ldg(&bias[n + 1]);
#pragma unroll
        for (int mt = 0; mt < 2; mt++) {
            int m = obase + m0 + 16 * mt + g;
            float v0 = acc[mt][nt][0] + b0, v1 = acc[mt][nt][1] + b1;
            v0 = v0 > 0.f ? v0 : 0.f;
            v1 = v1 > 0.f ? v1 : 0.f;
            *(__half2*)&out[(size_t)m * 1024 + n] = __floats2half2_rn(v0, v1);
            float v2 = acc[mt][nt][2] + b0, v3 = acc[mt][nt][3] + b1;
            v2 = v2 > 0.f ? v2 : 0.f;
            v3 = v3 > 0.f ? v3 : 0.f;
            *(__half2*)&out[(size_t)(m + 8) * 1024 + n] = __floats2half2_rn(v2, v3);
        }
    }
}

// =====================================================================
// V-mean phase 1: partial sums. grid (16h, BB, 16 chunks), 256 thr.
// =====================================================================
__global__ void __launch_bounds__(256) vpart_kernel() {
    __shared__ float part[4][64];
    const int h = blockIdx.x, b = blockIdx.y, chn = blockIdx.z;
    const int d = threadIdx.x & 63, r0 = threadIdx.x >> 6;

    float sum = 0.0f;
    const __half* vp = g_V + (size_t)(b * 2048 + chn * 128 + r0) * 1024 + h * 64 + d;
#pragma unroll 8
    for (int k = 0; k < 32; k++) sum += __half2float(vp[(size_t)(4 * k) * 1024]);
    part[r0][d] = sum;
    __syncthreads();
    if (r0 == 0)
        g_vpart[b][h][chn][d] = part[0][d] + part[1][d] + part[2][d] + part[3][d];
}

// =====================================================================
// V-mean phase 2: PRE-FILL the entire output with mean(V)+residual,
// fully coalesced float4. attn_mma later overwrites unmasked positions.
// grid (16h, BB, 8 row-slices of 16), 256 thr (1024 cols / 4 per thread).
// =====================================================================
__global__ void __launch_bounds__(256) vfill_kernel(const float* __restrict__ queries,
                                                    float* __restrict__ out) {
    __shared__ float mean[64];
    const int h = blockIdx.x, b = blockIdx.y, sl = blockIdx.z;
    const int tid = threadIdx.x;

    if (tid < 64) {
        float s = 0.0f;
#pragma unroll
        for (int c = 0; c < 16; c++) s += g_vpart[b][h][c][tid];
        mean[tid] = s * (1.0f / 2048.0f);
    }
    __syncthreads();

    const int c4 = tid * 4;
#pragma unroll
    for (int r = 0; r < 16; r++) {
        const int rr = 16 * sl + r;          // 0..127 within this head's rows
        const int srow = 128 * h + rr;       // rr = 2d + e
        const float mv = mean[rr >> 1];
        const size_t off = (size_t)(b * 2048 + srow) * 1024 + c4;
        float4 qv = *(const float4*)&queries[off];
        *(float4*)&out[off] = make_float4(qv.x + mv, qv.y + mv, qv.z + mv, qv.w + mv);
    }
}

// =====================================================================
// Flash attention over COMPACTED unmasked queries, scattered epilogue
// overwrites the pre-filled output at unmasked positions.
// =====================================================================
#define KST 72
#define OST 68
#define STAGE_H (64 * KST)
#define ATTN_SMEM ((6 * STAGE_H + 128 * KST) * 2)

__global__ void __launch_bounds__(256) attn_mma(const float* __restrict__ queries,
                                                float* __restrict__ out) {
    const int b = blockIdx.z, h = blockIdx.y;
    const int q0 = blockIdx.x * 128;
    const int nu = g_ncnt[b];
    if (q0 >= nu) return;  // inactive tile

    extern __shared__ __align__(16) char smbase[];
    __half* KB = (__half*)smbase;
    __half* VB = (__half*)smbase + 3 * STAGE_H;
    __half* Qs = (__half*)smbase + 6 * STAGE_H;
    float* So = (float*)smbase;
    __shared__ int sidx[128];

    const int tid = threadIdx.x;
    const int warp = tid >> 5, lane = tid & 31;
    const int g = lane >> 2, tig = lane & 3;
    const int qw = warp * 16;

    if (tid < 128) sidx[tid] = (q0 + tid < nu) ? g_qidx[b][q0 + tid] : -1;

    const int crow = tid >> 2;
    const int ccol = (tid & 3) * 16;
    const unsigned kdst = sptr(&KB[crow * KST + ccol]);
    const unsigned vdst = sptr(&VB[crow * KST + ccol]);

#pragma unroll
    for (int p = 0; p < 2; p++) {
        const size_t gofs = (size_t)(b * 2048 + p * 64 + crow) * 1024 + h * 64 + ccol;
        const unsigned soff = p * (STAGE_H * 2);
        cpa16(kdst + soff, g_K + gofs);
        cpa16(kdst + soff + 16, g_K + gofs + 8);
        cpa16(vdst + soff, g_V + gofs);
        cpa16(vdst + soff + 16, g_V + gofs + 8);
        asm volatile("cp.async.commit_group;");
    }

    // stage Q (compacted rows; scaled by 0.125*log2e), frags to registers
    {
        int row = tid >> 1;
        int koff = (tid & 1) * 32;
        const __half* qsrc = g_Q + (size_t)(b * 2048 + q0 + row) * 1024 + h * 64 + koff;
        const float qs = 0.125f * 1.4426950408889634f;
        const __half2 sc = __floats2half2_rn(qs, qs);
        __half2 v[16];
        *(uint4*)&v[0] = *(const uint4*)&qsrc[0];
        *(uint4*)&v[4] = *(const uint4*)&qsrc[8];
        *(uint4*)&v[8] = *(const uint4*)&qsrc[16];
        *(uint4*)&v[12] = *(const uint4*)&qsrc[24];
#pragma unroll
        for (int j = 0; j < 16; j++) v[j] = __hmul2(v[j], sc);
        *(uint4*)&Qs[row * KST + koff] = *(uint4*)&v[0];
        *(uint4*)&Qs[row * KST + koff + 8] = *(uint4*)&v[4];
        *(uint4*)&Qs[row * KST + koff + 16] = *(uint4*)&v[8];
        *(uint4*)&Qs[row * KST + koff + 24] = *(uint4*)&v[12];
    }
    __syncwarp();
    unsigned qf[4][4];
    {
        unsigned qa = sptr(&Qs[(qw + (lane & 15)) * KST + (lane >> 4) * 8]);
#pragma unroll
        for (int ks = 0; ks < 4; ks++)
            ldsm4(qf[ks][0], qf[ks][1], qf[ks][2], qf[ks][3], qa + ks * 32);
    }

    float mA = -1e30f, mB = -1e30f, lA = 0.0f, lB = 0.0f;
    float o[8][4];
#pragma unroll
    for (int nt = 0; nt < 8; nt++)
#pragma unroll
        for (int i = 0; i < 4; i++) o[nt][i] = 0.0f;

    const unsigned kb0 = sptr(&KB[(8 * (lane >> 4) + (lane & 7)) * KST + ((lane >> 3) & 1) * 8]);
    const unsigned vb0 = sptr(&VB[(8 * ((lane >> 3) & 1) + (lane & 7)) * KST + (lane >> 4) * 8]);

    int st = 0, st2 = 2;
    for (int jt = 0; jt < 32; jt++) {
        asm volatile("cp.async.wait_group 1;" ::: "memory");
        __syncthreads();

        if (jt + 2 < 32) {
            const size_t gofs = (size_t)(b * 2048 + (jt + 2) * 64 + crow) * 1024 + h * 64 + ccol;
            const unsigned soff = st2 * (STAGE_H * 2);
            cpa16(kdst + soff, g_K + gofs);
            cpa16(kdst + soff + 16, g_K + gofs + 8);
            cpa16(vdst + soff, g_V + gofs);
            cpa16(vdst + soff + 16, g_V + gofs + 8);
        }
        asm volatile("cp.async.commit_group;");

        const unsigned kb = kb0 + st * (STAGE_H * 2);
        float s[8][4];
#pragma unroll
        for (int nt = 0; nt < 8; nt++)
#pragma unroll
            for (int i = 0; i < 4; i++) s[nt][i] = 0.0f;
#pragma unroll
        for (int ks = 0; ks < 4; ks++) {
#pragma unroll
            for (int j = 0; j < 4; j++) {
                unsigned bfr[4];
                ldsm4(bfr[0], bfr[1], bfr[2], bfr[3], kb + j * (16 * KST * 2) + ks * 32);
                mma16(s[2 * j], qf[ks], bfr[0], bfr[1]);
                mma16(s[2 * j + 1], qf[ks], bfr[2], bfr[3]);
            }
        }

        float mxA = s[0][0], mxB = s[0][2];
#pragma unroll
        for (int nt = 0; nt < 8; nt++) {
            mxA = fmaxf(mxA, fmaxf(s[nt][0], s[nt][1]));
            mxB = fmaxf(mxB, fmaxf(s[nt][2], s[nt][3]));
        }
        mxA = fmaxf(mxA, __shfl_xor_sync(0xffffffffu, mxA, 1));
        mxA = fmaxf(mxA, __shfl_xor_sync(0xffffffffu, mxA, 2));
        mxB = fmaxf(mxB, __shfl_xor_sync(0xffffffffu, mxB, 1));
        mxB = fmaxf(mxB, __shfl_xor_sync(0xffffffffu, mxB, 2));
        float mnA = fmaxf(mA, mxA), mnB = fmaxf(mB, mxB);
        float cA = ex2(mA - mnA), cB = ex2(mB - mnB);
        mA = mnA; mB = mnB;
        float sumA = 0.0f, sumB = 0.0f;
#pragma unroll
        for (int nt = 0; nt < 8; nt++) {
            s[nt][0] = ex2(s[nt][0] - mnA);
            s[nt][1] = ex2(s[nt][1] - mnA);
            s[nt][2] = ex2(s[nt][2] - mnB);
            s[nt][3] = ex2(s[nt][3] - mnB);
            sumA += s[nt][0] + s[nt][1];
            sumB += s[nt][2] + s[nt][3];
        }
        sumA += __shfl_xor_sync(0xffffffffu, sumA, 1);
        sumA += __shfl_xor_sync(0xffffffffu, sumA, 2);
        sumB += __shfl_xor_sync(0xffffffffu, sumB, 1);
        sumB += __shfl_xor_sync(0xffffffffu, sumB, 2);
        lA = lA * cA + sumA;
        lB = lB * cB + sumB;

#pragma unroll
        for (int nt = 0; nt < 8; nt++) {
            o[nt][0] *= cA; o[nt][1] *= cA;
            o[nt][2] *= cB; o[nt][3] *= cB;
        }
        const unsigned vb = vb0 + st * (STAGE_H * 2);
#pragma unroll
        for (int ks = 0; ks < 4; ks++) {
            unsigned pa[4];
            pa[0] = h2u(s[2 * ks][0], s[2 * ks][1]);
            pa[1] = h2u(s[2 * ks][2], s[2 * ks][3]);
            pa[2] = h2u(s[2 * ks + 1][0], s[2 * ks + 1][1]);
            pa[3] = h2u(s[2 * ks + 1][2], s[2 * ks + 1][3]);
#pragma unroll
            for (int j = 0; j < 4; j++) {
                unsigned vfr[4];
                ldsm4t(vfr[0], vfr[1], vfr[2], vfr[3], vb + ks * (16 * KST * 2) + j * 32);
                mma16(o[2 * j], pa, vfr[0], vfr[1]);
                mma16(o[2 * j + 1], pa, vfr[2], vfr[3]);
            }
        }
        st = (st == 2) ? 0 : st + 1;
        st2 = (st2 == 2) ? 0 : st2 + 1;
    }

    __syncthreads();
    {
        float rA = 1.0f / lA, rB = 1.0f / lB;
#pragma unroll
        for (int nt = 0; nt < 8; nt++) {
            *(float2*)&So[(qw + g) * OST + 8 * nt + 2 * tig] =
                make_float2(o[nt][0] * rA, o[nt][1] * rA);
            *(float2*)&So[(qw + g + 8) * OST + 8 * nt + 2 * tig] =
                make_float2(o[nt][2] * rB, o[nt][3] * rB);
        }
    }
    __syncthreads();

    // scattered scrambled reshape + residual (overwrites pre-filled mean):
    //   out[b, 128h + 2d + (q>=1024), q % 1024] = O[i][d] + queries[...]
    const int dd = tid >> 2;  // d: 0..63
    const int c = tid & 3;
#pragma unroll 8
    for (int t = 0; t < 32; t++) {
        const int i = 4 * t + c;
        const int q = sidx[i];
        if (q >= 0) {
            const int srow = 128 * h + 2 * dd + (q >> 10);
            const size_t off = (size_t)(b * 2048 + srow) * 1024 + (q & 1023);
            out[off] = So[i * OST + dd] + queries[off];
        }
    }
}

// ---------------- launch ----------------
extern "C" void kernel_launch(void* const* d_in, const int* in_sizes, int n_in, void* d_out,
                              int out_size) {
    const float* queries = (const float*)d_in[0];
    const float* keys = (const float*)d_in[1];
    const float* values = (const float*)d_in[2];
    const int* amask = (const int*)d_in[3];
    const float* Wq = (const float*)d_in[4];
    const float* bq = (const float*)d_in[5];
    const float* Wk = (const float*)d_in[6];
    const float* bk = (const float*)d_in[7];
    const float* Wv = (const float*)d_in[8];
    const float* bv = (const float*)d_in[9];
    float* out = (float*)d_out;

    compact_kernel<<<BB, 32>>>(amask);

    dim3 gc(512, 6, 1);
    cvt_kernel<<<gc, 256>>>(queries, keys, values, Wq, Wk, Wv);

    cudaFuncSetAttribute(qkv_gemm, cudaFuncAttributeMaxDynamicSharedMemorySize, GEMM_SMEM);
    dim3 g1(8, 32, 3);
    qkv_gemm<<<g1, 256, GEMM_SMEM>>>(bq, bk, bv);

    vpart_kernel<<<dim3(16, BB, 16), 256>>>();
    vfill_kernel<<<dim3(16, BB, 8), 256>>>(queries, out);  // pre-fill ALL of out

    cudaFuncSetAttribute(attn_mma, cudaFuncAttributeMaxDynamicSharedMemorySize, ATTN_SMEM);
    dim3 g2(16, 16, BB);
    attn_mma<<<g2, 256, ATTN_SMEM>>>(queries, out);  // overwrites unmasked positions
}

// round 12
// speedup vs baseline: 1.7938x; 1.0119x over previous
#include <cuda_runtime.h>
#include <cuda_fp16.h>

// Problem constants
#define BB 2
#define SS 2048
#define DD 1024

// fp16 staging buffers + compaction lists (device globals: no allocation)
__device__ __half g_Q[BB * SS * DD];   // compacted unmasked Q rows
__device__ __half g_K[BB * SS * DD];
__device__ __half g_V[BB * SS * DD];
__device__ __half g_Xh[3][BB * SS * DD];  // fp16 inputs (X_q compacted)
__device__ __half g_Wh[3][DD * DD];
__device__ int g_qidx[BB][SS];  // unmasked query indices (ascending)
__device__ int g_ncnt[BB];      // # unmasked
__device__ float g_vsum[BB][DD];  // column sums of post-relu V (atomic)

// ---------- helpers ----------
__device__ __forceinline__ unsigned sptr(const void* p) {
    return (unsigned)__cvta_generic_to_shared(p);
}
__device__ __forceinline__ void ldsm4(unsigned& r0, unsigned& r1, unsigned& r2, unsigned& r3,
                                      unsigned addr) {
    asm volatile("ldmatrix.sync.aligned.m8n8.x4.shared.b16 {%0,%1,%2,%3}, [%4];"
                 : "=r"(r0), "=r"(r1), "=r"(r2), "=r"(r3)
                 : "r"(addr));
}
__device__ __forceinline__ void ldsm4t(unsigned& r0, unsigned& r1, unsigned& r2, unsigned& r3,
                                       unsigned addr) {
    asm volatile("ldmatrix.sync.aligned.m8n8.x4.trans.shared.b16 {%0,%1,%2,%3}, [%4];"
                 : "=r"(r0), "=r"(r1), "=r"(r2), "=r"(r3)
                 : "r"(addr));
}
__device__ __forceinline__ void mma16(float c[4], const unsigned a[4], unsigned b0, unsigned b1) {
    asm volatile(
        "mma.sync.aligned.m16n8k16.row.col.f32.f16.f16.f32 "
        "{%0,%1,%2,%3},{%4,%5,%6,%7},{%8,%9},{%0,%1,%2,%3};"
        : "+f"(c[0]), "+f"(c[1]), "+f"(c[2]), "+f"(c[3])
        : "r"(a[0]), "r"(a[1]), "r"(a[2]), "r"(a[3]), "r"(b0), "r"(b1));
}
__device__ __forceinline__ void cpa16(unsigned s, const void* g) {
    asm volatile("cp.async.cg.shared.global [%0], [%1], 16;" ::"r"(s), "l"(g));
}
__device__ __forceinline__ unsigned h2u(float a, float b) {
    __half2 h = __floats2half2_rn(a, b);
    return *(unsigned*)&h;
}
__device__ __forceinline__ float ex2(float x) {
    float y;
    asm("ex2.approx.ftz.f32 %0, %1;" : "=f"(y) : "f"(x));
    return y;
}

// =====================================================================
// Mask compaction (+ zero g_vsum): one warp per batch.
// =====================================================================
__global__ void compact_kernel(const int* __restrict__ amask) {
    const int b = blockIdx.x;
    const int lane = threadIdx.x;
    int nu = 0;
    for (int i0 = 0; i0 < SS; i0 += 32) {
        int m = amask[b * SS + i0 + lane] != 0;
        unsigned bal = __ballot_sync(0xffffffffu, m);
        unsigned below = (1u << lane) - 1u;
        if (m) g_qidx[b][nu + __popc(bal & below)] = i0 + lane;
        nu += __popc(bal);
    }
    if (lane == 0) g_ncnt[b] = nu;
    for (int i = lane; i < DD; i += 32) g_vsum[b][i] = 0.0f;
}

// =====================================================================
// fp32 -> fp16 conversion. Queries (sel 0): gather unmasked rows only,
// write COMPACTED. Others: straight elementwise.
// =====================================================================
__global__ void __launch_bounds__(256) cvt_kernel(
    const float* __restrict__ q, const float* __restrict__ k, const float* __restrict__ v,
    const float* __restrict__ wq, const float* __restrict__ wk, const float* __restrict__ wv) {
    const int sel = blockIdx.y;
    const int stride = gridDim.x * blockDim.x;

    if (sel == 0) {  // compacted gather of unmasked query rows
        const int n4 = BB * SS * DD / 4;
        for (int i = blockIdx.x * blockDim.x + threadIdx.x; i < n4; i += stride) {
            const int row = i >> 8;          // 256 float4 per row
            const int col = i & 255;
            const int b = row >> 11, rb = row & 2047;
            if (rb >= g_ncnt[b]) continue;
            const int srow = b * 2048 + g_qidx[b][rb];
            float4 f = ((const float4*)q)[srow * 256 + col];
            __half2 h0 = __floats2half2_rn(f.x, f.y);
            __half2 h1 = __floats2half2_rn(f.z, f.w);
            uint2 o;
            o.x = *(unsigned*)&h0;
            o.y = *(unsigned*)&h1;
            ((uint2*)g_Xh[0])[(size_t)row * 256 + col] = o;
        }
        return;
    }

    const float* src;
    __half* dst;
    int n4;
    switch (sel) {
        case 1: src = k;  dst = g_Xh[1]; n4 = BB * SS * DD / 4; break;
        case 2: src = v;  dst = g_Xh[2]; n4 = BB * SS * DD / 4; break;
        case 3: src = wq; dst = g_Wh[0]; n4 = DD * DD / 4; break;
        case 4: src = wk; dst = g_Wh[1]; n4 = DD * DD / 4; break;
        default: src = wv; dst = g_Wh[2]; n4 = DD * DD / 4; break;
    }
    for (int i = blockIdx.x * blockDim.x + threadIdx.x; i < n4; i += stride) {
        float4 f = ((const float4*)src)[i];
        __half2 h0 = __floats2half2_rn(f.x, f.y);
        __half2 h1 = __floats2half2_rn(f.z, f.w);
        uint2 o;
        o.x = *(unsigned*)&h0;
        o.y = *(unsigned*)&h1;
        ((uint2*)dst)[i] = o;
    }
}

// =====================================================================
// QKV projection (fp16): out = relu(X @ W^T + b). z=0: compacted Q rows.
// z=2 (V): epilogue also accumulates column sums into g_vsum (atomics).
// 3-stage cp.async pipeline; ldmatrix + m16n8k16.
// =====================================================================
#define QST 72
#define QSTG (128 * QST)
#define GEMM_SMEM (6 * QSTG * 2)

__global__ void __launch_bounds__(256, 2) qkv_gemm(
    const float* __restrict__ bq, const float* __restrict__ bk, const float* __restrict__ bv) {
    const int z = blockIdx.z;
    const __half* X = g_Xh[z];
    const __half* W = g_Wh[z];
    const float* bias = (z == 0) ? bq : (z == 1) ? bk : bv;
    __half* out = (z == 0) ? g_Q : (z == 1) ? g_K : g_V;

    const int tid = threadIdx.x;
    const int my = blockIdx.y;
    const int crow = tid >> 1;        // loader row within tile
    const int ccol = (tid & 1) * 32;  // loader col (halves)

    int obase, grow;
    if (z == 0) {
        const int bqb = my >> 4, tq = my & 15;
        const int nu = g_ncnt[bqb];
        if (tq * 128 >= nu) return;  // inactive tile
        obase = bqb * 2048 + tq * 128;
        int i = tq * 128 + crow;
        if (i >= nu) i = nu - 1;  // clamp (finite data, results discarded)
        grow = bqb * 2048 + i;    // compacted input space
    } else {
        obase = my * 128;
        grow = my * 128 + crow;
    }

    extern __shared__ __align__(16) char smraw[];
    __half* XB = (__half*)smraw;
    __half* WB = (__half*)smraw + 3 * QSTG;

    const int warp = tid >> 5, lane = tid & 31;
    const int g = lane >> 2, tig = lane & 3;
    const int m0 = (warp >> 1) * 32;
    const int n0 = (warp & 1) * 64;
    const int bn = blockIdx.x * 128;

    const unsigned xdst = sptr(&XB[crow * QST + ccol]);
    const unsigned wdst = sptr(&WB[crow * QST + ccol]);
    const size_t xrow = (size_t)grow * 1024 + ccol;
    const size_t wrow = (size_t)(bn + crow) * 1024 + ccol;

    float acc[2][8][4];
#pragma unroll
    for (int mt = 0; mt < 2; mt++)
#pragma unroll
        for (int nt = 0; nt < 8; nt++)
#pragma unroll
            for (int i = 0; i < 4; i++) acc[mt][nt][i] = 0.0f;

    const unsigned xa0 = sptr(&XB[(m0 + (lane & 15)) * QST + (lane >> 4) * 8]);
    const unsigned xa1 = sptr(&XB[(m0 + 16 + (lane & 15)) * QST + (lane >> 4) * 8]);
    const unsigned wbb = sptr(&WB[(n0 + 8 * (lane >> 4) + (lane & 7)) * QST + ((lane >> 3) & 1) * 8]);

#pragma unroll
    for (int p = 0; p < 2; p++) {
        const unsigned soff = p * (QSTG * 2);
        const int k0 = p * 64;
#pragma unroll
        for (int c = 0; c < 4; c++) {
            cpa16(xdst + soff + c * 16, X + xrow + k0 + c * 8);
            cpa16(wdst + soff + c * 16, W + wrow + k0 + c * 8);
        }
        asm volatile("cp.async.commit_group;");
    }

    int st = 0, st2 = 2;
    for (int it = 0; it < 16; it++) {
        asm volatile("cp.async.wait_group 1;" ::: "memory");
        __syncthreads();

        if (it + 2 < 16) {
            const int k0 = (it + 2) * 64;
            const unsigned soff = st2 * (QSTG * 2);
#pragma unroll
            for (int c = 0; c < 4; c++) {
                cpa16(xdst + soff + c * 16, X + xrow + k0 + c * 8);
                cpa16(wdst + soff + c * 16, W + wrow + k0 + c * 8);
            }
        }
        asm volatile("cp.async.commit_group;");

        const unsigned sa = st * (QSTG * 2);
#pragma unroll
        for (int ks = 0; ks < 4; ks++) {
            unsigned a0[4], a1[4];
            ldsm4(a0[0], a0[1], a0[2], a0[3], xa0 + sa + ks * 32);
            ldsm4(a1[0], a1[1], a1[2], a1[3], xa1 + sa + ks * 32);
#pragma unroll
            for (int j = 0; j < 4; j++) {
                unsigned b[4];
                ldsm4(b[0], b[1], b[2], b[3], wbb + sa + j * (16 * QST * 2) + ks * 32);
                mma16(acc[0][2 * j], a0, b[0], b[1]);
                mma16(acc[0][2 * j + 1], a0, b[2], b[3]);
                mma16(acc[1][2 * j], a1, b[0], b[1]);
                mma16(acc[1][2 * j + 1], a1, b[2], b[3]);
            }
        }
        st = (st == 2) ? 0 : st + 1;
        st2 = (st2 == 2) ? 0 : st2 + 1;
    }

    // epilogue: bias + relu + fp16 store (+ V column sums for z==2)
    const int vb2 = obase >> 11;  // batch of this tile's rows (z==2 path)
#pragma unroll
    for (int nt = 0; nt < 8; nt++) {
        int n = bn + n0 + 8 * nt + 2 * tig;
        float b0 = __ldg(&bias[n]), b1 = __ldg(&bias[n + 1]);
        float cs0 = 0.0f, cs1 = 0.0f;  // column sums (post-relu)
#pragma unroll
        for (int mt = 0; mt < 2; mt++) {
            int m = obase + m0 + 16 * mt + g;
            float v0 = acc[mt][nt][0] + b0, v1 = acc[mt][nt][1] + b1;
            v0 = v0 > 0.f ? v0 : 0.f;
            v1 = v1 > 0.f ? v1 : 0.f;
            *(__half2*)&out[(size_t)m * 1024 + n] = __floats2half2_rn(v0, v1);
            float v2 = acc[mt][nt][2] + b0, v3 = acc[mt][nt][3] + b1;
            v2 = v2 > 0.f ? v2 : 0.f;
            v3 = v3 > 0.f ? v3 : 0.f;
            *(__half2*)&out[(size_t)(m + 8) * 1024 + n] = __floats2half2_rn(v2, v3);
            cs0 += v0 + v2;
            cs1 += v1 + v3;
        }
        if (z == 2) {
            // reduce across the 8 m-groups (lanes differing in bits [2:5))
#pragma unroll
            for (int o = 4; o < 32; o <<= 1) {
                cs0 += __shfl_xor_sync(0xffffffffu, cs0, o);
                cs1 += __shfl_xor_sync(0xffffffffu, cs1, o);
            }
            if (g == 0) {
                atomicAdd(&g_vsum[vb2][n], cs0);
                atomicAdd(&g_vsum[vb2][n + 1], cs1);
            }
        }
    }
}

// =====================================================================
// PRE-FILL the entire output with mean(V)+residual, coalesced float4.
// attn_mma later overwrites unmasked positions.
// =====================================================================
__global__ void __launch_bounds__(256) vfill_kernel(const float* __restrict__ queries,
                                                    float* __restrict__ out) {
    __shared__ float mean[64];
    const int h = blockIdx.x, b = blockIdx.y, sl = blockIdx.z;
    const int tid = threadIdx.x;

    if (tid < 64) mean[tid] = g_vsum[b][h * 64 + tid] * (1.0f / 2048.0f);
    __syncthreads();

    const int c4 = tid * 4;
#pragma unroll
    for (int r = 0; r < 16; r++) {
        const int rr = 16 * sl + r;          // 0..127 within this head's rows
        const int srow = 128 * h + rr;       // rr = 2d + e
        const float mv = mean[rr >> 1];
        const size_t off = (size_t)(b * 2048 + srow) * 1024 + c4;
        float4 qv = *(const float4*)&queries[off];
        *(float4*)&out[off] = make_float4(qv.x + mv, qv.y + mv, qv.z + mv, qv.w + mv);
    }
}

// =====================================================================
// Flash attention over COMPACTED unmasked queries, scattered epilogue
// overwrites the pre-filled output at unmasked positions.
// =====================================================================
#define KST 72
#define OST 68
#define STAGE_H (64 * KST)
#define ATTN_SMEM ((6 * STAGE_H + 128 * KST) * 2)

__global__ void __launch_bounds__(256) attn_mma(const float* __restrict__ queries,
                                                float* __restrict__ out) {
    const int b = blockIdx.z, h = blockIdx.y;
    const int q0 = blockIdx.x * 128;
    const int nu = g_ncnt[b];
    if (q0 >= nu) return;  // inactive tile

    extern __shared__ __align__(16) char smbase[];
    __half* KB = (__half*)smbase;
    __half* VB = (__half*)smbase + 3 * STAGE_H;
    __half* Qs = (__half*)smbase + 6 * STAGE_H;
    float* So = (float*)smbase;
    __shared__ int sidx[128];

    const int tid = threadIdx.x;
    const int warp = tid >> 5, lane = tid & 31;
    const int g = lane >> 2, tig = lane & 3;
    const int qw = warp * 16;

    if (tid < 128) sidx[tid] = (q0 + tid < nu) ? g_qidx[b][q0 + tid] : -1;

    const int crow = tid >> 2;
    const int ccol = (tid & 3) * 16;
    const unsigned kdst = sptr(&KB[crow * KST + ccol]);
    const unsigned vdst = sptr(&VB[crow * KST + ccol]);

#pragma unroll
    for (int p = 0; p < 2; p++) {
        const size_t gofs = (size_t)(b * 2048 + p * 64 + crow) * 1024 + h * 64 + ccol;
        const unsigned soff = p * (STAGE_H * 2);
        cpa16(kdst + soff, g_K + gofs);
        cpa16(kdst + soff + 16, g_K + gofs + 8);
        cpa16(vdst + soff, g_V + gofs);
        cpa16(vdst + soff + 16, g_V + gofs + 8);
        asm volatile("cp.async.commit_group;");
    }

    // stage Q (compacted rows; scaled by 0.125*log2e), frags to registers
    {
        int row = tid >> 1;
        int koff = (tid & 1) * 32;
        const __half* qsrc = g_Q + (size_t)(b * 2048 + q0 + row) * 1024 + h * 64 + koff;
        const float qs = 0.125f * 1.4426950408889634f;
        const __half2 sc = __floats2half2_rn(qs, qs);
        __half2 v[16];
        *(uint4*)&v[0] = *(const uint4*)&qsrc[0];
        *(uint4*)&v[4] = *(const uint4*)&qsrc[8];
        *(uint4*)&v[8] = *(const uint4*)&qsrc[16];
        *(uint4*)&v[12] = *(const uint4*)&qsrc[24];
#pragma unroll
        for (int j = 0; j < 16; j++) v[j] = __hmul2(v[j], sc);
        *(uint4*)&Qs[row * KST + koff] = *(uint4*)&v[0];
        *(uint4*)&Qs[row * KST + koff + 8] = *(uint4*)&v[4];
        *(uint4*)&Qs[row * KST + koff + 16] = *(uint4*)&v[8];
        *(uint4*)&Qs[row * KST + koff + 24] = *(uint4*)&v[12];
    }
    __syncwarp();
    unsigned qf[4][4];
    {
        unsigned qa = sptr(&Qs[(qw + (lane & 15)) * KST + (lane >> 4) * 8]);
#pragma unroll
        for (int ks = 0; ks < 4; ks++)
            ldsm4(qf[ks][0], qf[ks][1], qf[ks][2], qf[ks][3], qa + ks * 32);
    }

    float mA = -1e30f, mB = -1e30f, lA = 0.0f, lB = 0.0f;
    float o[8][4];
#pragma unroll
    for (int nt = 0; nt < 8; nt++)
#pragma unroll
        for (int i = 0; i < 4; i++) o[nt][i] = 0.0f;

    const unsigned kb0 = sptr(&KB[(8 * (lane >> 4) + (lane & 7)) * KST + ((lane >> 3) & 1) * 8]);
    const unsigned vb0 = sptr(&VB[(8 * ((lane >> 3) & 1) + (lane & 7)) * KST + (lane >> 4) * 8]);

    int st = 0, st2 = 2;
    for (int jt = 0; jt < 32; jt++) {
        asm volatile("cp.async.wait_group 1;" ::: "memory");
        __syncthreads();

        if (jt + 2 < 32) {
            const size_t gofs = (size_t)(b * 2048 + (jt + 2) * 64 + crow) * 1024 + h * 64 + ccol;
            const unsigned soff = st2 * (STAGE_H * 2);
            cpa16(kdst + soff, g_K + gofs);
            cpa16(kdst + soff + 16, g_K + gofs + 8);
            cpa16(vdst + soff, g_V + gofs);
            cpa16(vdst + soff + 16, g_V + gofs + 8);
        }
        asm volatile("cp.async.commit_group;");

        const unsigned kb = kb0 + st * (STAGE_H * 2);
        float s[8][4];
#pragma unroll
        for (int nt = 0; nt < 8; nt++)
#pragma unroll
            for (int i = 0; i < 4; i++) s[nt][i] = 0.0f;
#pragma unroll
        for (int ks = 0; ks < 4; ks++) {
#pragma unroll
            for (int j = 0; j < 4; j++) {
                unsigned bfr[4];
                ldsm4(bfr[0], bfr[1], bfr[2], bfr[3], kb + j * (16 * KST * 2) + ks * 32);
                mma16(s[2 * j], qf[ks], bfr[0], bfr[1]);
                mma16(s[2 * j + 1], qf[ks], bfr[2], bfr[3]);
            }
        }

        float mxA = s[0][0], mxB = s[0][2];
#pragma unroll
        for (int nt = 0; nt < 8; nt++) {
            mxA = fmaxf(mxA, fmaxf(s[nt][0], s[nt][1]));
            mxB = fmaxf(mxB, fmaxf(s[nt][2], s[nt][3]));
        }
        mxA = fmaxf(mxA, __shfl_xor_sync(0xffffffffu, mxA, 1));
        mxA = fmaxf(mxA, __shfl_xor_sync(0xffffffffu, mxA, 2));
        mxB = fmaxf(mxB, __shfl_xor_sync(0xffffffffu, mxB, 1));
        mxB = fmaxf(mxB, __shfl_xor_sync(0xffffffffu, mxB, 2));
        float mnA = fmaxf(mA, mxA), mnB = fmaxf(mB, mxB);
        float cA = ex2(mA - mnA), cB = ex2(mB - mnB);
        mA = mnA; mB = mnB;
        float sumA = 0.0f, sumB = 0.0f;
#pragma unroll
        for (int nt = 0; nt < 8; nt++) {
            s[nt][0] = ex2(s[nt][0] - mnA);
            s[nt][1] = ex2(s[nt][1] - mnA);
            s[nt][2] = ex2(s[nt][2] - mnB);
            s[nt][3] = ex2(s[nt][3] - mnB);
            sumA += s[nt][0] + s[nt][1];
            sumB += s[nt][2] + s[nt][3];
        }
        sumA += __shfl_xor_sync(0xffffffffu, sumA, 1);
        sumA += __shfl_xor_sync(0xffffffffu, sumA, 2);
        sumB += __shfl_xor_sync(0xffffffffu, sumB, 1);
        sumB += __shfl_xor_sync(0xffffffffu, sumB, 2);
        lA = lA * cA + sumA;
        lB = lB * cB + sumB;

#pragma unroll
        for (int nt = 0; nt < 8; nt++) {
            o[nt][0] *= cA; o[nt][1] *= cA;
            o[nt][2] *= cB; o[nt][3] *= cB;
        }
        const unsigned vb = vb0 + st * (STAGE_H * 2);
#pragma unroll
        for (int ks = 0; ks < 4; ks++) {
            unsigned pa[4];
            pa[0] = h2u(s[2 * ks][0], s[2 * ks][1]);
            pa[1] = h2u(s[2 * ks][2], s[2 * ks][3]);
            pa[2] = h2u(s[2 * ks + 1][0], s[2 * ks + 1][1]);
            pa[3] = h2u(s[2 * ks + 1][2], s[2 * ks + 1][3]);
#pragma unroll
            for (int j = 0; j < 4; j++) {
                unsigned vfr[4];
                ldsm4t(vfr[0], vfr[1], vfr[2], vfr[3], vb + ks * (16 * KST * 2) + j * 32);
                mma16(o[2 * j], pa, vfr[0], vfr[1]);
                mma16(o[2 * j + 1], pa, vfr[2], vfr[3]);
            }
        }
        st = (st == 2) ? 0 : st + 1;
        st2 = (st2 == 2) ? 0 : st2 + 1;
    }

    __syncthreads();
    {
        float rA = 1.0f / lA, rB = 1.0f / lB;
#pragma unroll
        for (int nt = 0; nt < 8; nt++) {
            *(float2*)&So[(qw + g) * OST + 8 * nt + 2 * tig] =
                make_float2(o[nt][0] * rA, o[nt][1] * rA);
            *(float2*)&So[(qw + g + 8) * OST + 8 * nt + 2 * tig] =
                make_float2(o[nt][2] * rB, o[nt][3] * rB);
        }
    }
    __syncthreads();

    // scattered scrambled reshape + residual (overwrites pre-filled mean):
    //   out[b, 128h + 2d + (q>=1024), q % 1024] = O[i][d] + queries[...]
    const int dd = tid >> 2;  // d: 0..63
    const int c = tid & 3;
#pragma unroll 8
    for (int t = 0; t < 32; t++) {
        const int i = 4 * t + c;
        const int q = sidx[i];
        if (q >= 0) {
            const int srow = 128 * h + 2 * dd + (q >> 10);
            const size_t off = (size_t)(b * 2048 + srow) * 1024 + (q & 1023);
            out[off] = So[i * OST + dd] + queries[off];
        }
    }
}

// ---------------- launch ----------------
extern "C" void kernel_launch(void* const* d_in, const int* in_sizes, int n_in, void* d_out,
                              int out_size) {
    const float* queries = (const float*)d_in[0];
    const float* keys = (const float*)d_in[1];
    const float* values = (const float*)d_in[2];
    const int* amask = (const int*)d_in[3];
    const float* Wq = (const float*)d_in[4];
    const float* bq = (const float*)d_in[5];
    const float* Wk = (const float*)d_in[6];
    const float* bk = (const float*)d_in[7];
    const float* Wv = (const float*)d_in[8];
    const float* bv = (const float*)d_in[9];
    float* out = (float*)d_out;

    compact_kernel<<<BB, 32>>>(amask);  // also zeros g_vsum

    dim3 gc(512, 6, 1);
    cvt_kernel<<<gc, 256>>>(queries, keys, values, Wq, Wk, Wv);

    cudaFuncSetAttribute(qkv_gemm, cudaFuncAttributeMaxDynamicSharedMemorySize, GEMM_SMEM);
    dim3 g1(8, 32, 3);
    qkv_gemm<<<g1, 256, GEMM_SMEM>>>(bq, bk, bv);  // V slice also fills g_vsum

    vfill_kernel<<<dim3(16, BB, 8), 256>>>(queries, out);  // pre-fill ALL of out

    cudaFuncSetAttribute(attn_mma, cudaFuncAttributeMaxDynamicSharedMemorySize, ATTN_SMEM);
    dim3 g2(16, 16, BB);
    attn_mma<<<g2, 256, ATTN_SMEM>>>(queries, out);  // overwrites unmasked positions
}

// round 13
// speedup vs baseline: 1.8259x; 1.0179x over previous
#include <cuda_runtime.h>
#include <cuda_fp16.h>

// Problem constants
#define BB 2
#define SS 2048
#define DD 1024

// fp16 staging buffers + compaction lists (device globals: no allocation)
__device__ __half g_Q[BB * SS * DD];   // compacted unmasked Q rows
__device__ __half g_K[BB * SS * DD];
__device__ __half g_V[BB * SS * DD];
__device__ __half g_Xh[3][BB * SS * DD];  // fp16 inputs (X_q compacted)
__device__ __half g_Wh[3][DD * DD];
__device__ int g_qidx[BB][SS];  // unmasked query indices (ascending)
__device__ int g_ncnt[BB];      // # unmasked
__device__ float g_vsum[BB][DD];  // column sums of post-relu V (atomic)

// ---------- helpers ----------
__device__ __forceinline__ unsigned sptr(const void* p) {
    return (unsigned)__cvta_generic_to_shared(p);
}
__device__ __forceinline__ void ldsm4(unsigned& r0, unsigned& r1, unsigned& r2, unsigned& r3,
                                      unsigned addr) {
    asm volatile("ldmatrix.sync.aligned.m8n8.x4.shared.b16 {%0,%1,%2,%3}, [%4];"
                 : "=r"(r0), "=r"(r1), "=r"(r2), "=r"(r3)
                 : "r"(addr));
}
__device__ __forceinline__ void ldsm4t(unsigned& r0, unsigned& r1, unsigned& r2, unsigned& r3,
                                       unsigned addr) {
    asm volatile("ldmatrix.sync.aligned.m8n8.x4.trans.shared.b16 {%0,%1,%2,%3}, [%4];"
                 : "=r"(r0), "=r"(r1), "=r"(r2), "=r"(r3)
                 : "r"(addr));
}
__device__ __forceinline__ void mma16(float c[4], const unsigned a[4], unsigned b0, unsigned b1) {
    asm volatile(
        "mma.sync.aligned.m16n8k16.row.col.f32.f16.f16.f32 "
        "{%0,%1,%2,%3},{%4,%5,%6,%7},{%8,%9},{%0,%1,%2,%3};"
        : "+f"(c[0]), "+f"(c[1]), "+f"(c[2]), "+f"(c[3])
        : "r"(a[0]), "r"(a[1]), "r"(a[2]), "r"(a[3]), "r"(b0), "r"(b1));
}
__device__ __forceinline__ void cpa16(unsigned s, const void* g) {
    asm volatile("cp.async.cg.shared.global [%0], [%1], 16;" ::"r"(s), "l"(g));
}
__device__ __forceinline__ unsigned h2u(float a, float b) {
    __half2 h = __floats2half2_rn(a, b);
    return *(unsigned*)&h;
}
__device__ __forceinline__ float ex2(float x) {
    float y;
    asm("ex2.approx.ftz.f32 %0, %1;" : "=f"(y) : "f"(x));
    return y;
}

// =====================================================================
// Mask compaction (+ zero g_vsum): one warp per batch.
// =====================================================================
__global__ void compact_kernel(const int* __restrict__ amask) {
    const int b = blockIdx.x;
    const int lane = threadIdx.x;
    int nu = 0;
    for (int i0 = 0; i0 < SS; i0 += 32) {
        int m = amask[b * SS + i0 + lane] != 0;
        unsigned bal = __ballot_sync(0xffffffffu, m);
        unsigned below = (1u << lane) - 1u;
        if (m) g_qidx[b][nu + __popc(bal & below)] = i0 + lane;
        nu += __popc(bal);
    }
    if (lane == 0) g_ncnt[b] = nu;
    for (int i = lane; i < DD; i += 32) g_vsum[b][i] = 0.0f;
}

// =====================================================================
// fp32 -> fp16 conversion. Queries (sel 0): gather unmasked rows only,
// write COMPACTED. Others: straight elementwise.
// =====================================================================
__global__ void __launch_bounds__(256) cvt_kernel(
    const float* __restrict__ q, const float* __restrict__ k, const float* __restrict__ v,
    const float* __restrict__ wq, const float* __restrict__ wk, const float* __restrict__ wv) {
    const int sel = blockIdx.y;
    const int stride = gridDim.x * blockDim.x;

    if (sel == 0) {  // compacted gather of unmasked query rows
        const int n4 = BB * SS * DD / 4;
        for (int i = blockIdx.x * blockDim.x + threadIdx.x; i < n4; i += stride) {
            const int row = i >> 8;          // 256 float4 per row
            const int col = i & 255;
            const int b = row >> 11, rb = row & 2047;
            if (rb >= g_ncnt[b]) continue;
            const int srow = b * 2048 + g_qidx[b][rb];
            float4 f = ((const float4*)q)[srow * 256 + col];
            __half2 h0 = __floats2half2_rn(f.x, f.y);
            __half2 h1 = __floats2half2_rn(f.z, f.w);
            uint2 o;
            o.x = *(unsigned*)&h0;
            o.y = *(unsigned*)&h1;
            ((uint2*)g_Xh[0])[(size_t)row * 256 + col] = o;
        }
        return;
    }

    const float* src;
    __half* dst;
    int n4;
    switch (sel) {
        case 1: src = k;  dst = g_Xh[1]; n4 = BB * SS * DD / 4; break;
        case 2: src = v;  dst = g_Xh[2]; n4 = BB * SS * DD / 4; break;
        case 3: src = wq; dst = g_Wh[0]; n4 = DD * DD / 4; break;
        case 4: src = wk; dst = g_Wh[1]; n4 = DD * DD / 4; break;
        default: src = wv; dst = g_Wh[2]; n4 = DD * DD / 4; break;
    }
    for (int i = blockIdx.x * blockDim.x + threadIdx.x; i < n4; i += stride) {
        float4 f = ((const float4*)src)[i];
        __half2 h0 = __floats2half2_rn(f.x, f.y);
        __half2 h1 = __floats2half2_rn(f.z, f.w);
        uint2 o;
        o.x = *(unsigned*)&h0;
        o.y = *(unsigned*)&h1;
        ((uint2*)dst)[i] = o;
    }
}

// =====================================================================
// QKV projection (fp16): out = relu(X @ W^T + b). z=0: compacted Q rows.
// z=2 (V): epilogue also accumulates column sums into g_vsum (atomics).
// 3-stage cp.async pipeline; ldmatrix + m16n8k16.
// =====================================================================
#define QST 72
#define QSTG (128 * QST)
#define GEMM_SMEM (6 * QSTG * 2)

__global__ void __launch_bounds__(256, 2) qkv_gemm(
    const float* __restrict__ bq, const float* __restrict__ bk, const float* __restrict__ bv) {
    const int z = blockIdx.z;
    const __half* X = g_Xh[z];
    const __half* W = g_Wh[z];
    const float* bias = (z == 0) ? bq : (z == 1) ? bk : bv;
    __half* out = (z == 0) ? g_Q : (z == 1) ? g_K : g_V;

    const int tid = threadIdx.x;
    const int my = blockIdx.y;
    const int crow = tid >> 1;        // loader row within tile
    const int ccol = (tid & 1) * 32;  // loader col (halves)

    int obase, grow;
    if (z == 0) {
        const int bqb = my >> 4, tq = my & 15;
        const int nu = g_ncnt[bqb];
        if (tq * 128 >= nu) return;  // inactive tile
        obase = bqb * 2048 + tq * 128;
        int i = tq * 128 + crow;
        if (i >= nu) i = nu - 1;  // clamp (finite data, results discarded)
        grow = bqb * 2048 + i;    // compacted input space
    } else {
        obase = my * 128;
        grow = my * 128 + crow;
    }

    extern __shared__ __align__(16) char smraw[];
    __half* XB = (__half*)smraw;
    __half* WB = (__half*)smraw + 3 * QSTG;

    const int warp = tid >> 5, lane = tid & 31;
    const int g = lane >> 2, tig = lane & 3;
    const int m0 = (warp >> 1) * 32;
    const int n0 = (warp & 1) * 64;
    const int bn = blockIdx.x * 128;

    const unsigned xdst = sptr(&XB[crow * QST + ccol]);
    const unsigned wdst = sptr(&WB[crow * QST + ccol]);
    const size_t xrow = (size_t)grow * 1024 + ccol;
    const size_t wrow = (size_t)(bn + crow) * 1024 + ccol;

    float acc[2][8][4];
#pragma unroll
    for (int mt = 0; mt < 2; mt++)
#pragma unroll
        for (int nt = 0; nt < 8; nt++)
#pragma unroll
            for (int i = 0; i < 4; i++) acc[mt][nt][i] = 0.0f;

    const unsigned xa0 = sptr(&XB[(m0 + (lane & 15)) * QST + (lane >> 4) * 8]);
    const unsigned xa1 = sptr(&XB[(m0 + 16 + (lane & 15)) * QST + (lane >> 4) * 8]);
    const unsigned wbb = sptr(&WB[(n0 + 8 * (lane >> 4) + (lane & 7)) * QST + ((lane >> 3) & 1) * 8]);

#pragma unroll
    for (int p = 0; p < 2; p++) {
        const unsigned soff = p * (QSTG * 2);
        const int k0 = p * 64;
#pragma unroll
        for (int c = 0; c < 4; c++) {
            cpa16(xdst + soff + c * 16, X + xrow + k0 + c * 8);
            cpa16(wdst + soff + c * 16, W + wrow + k0 + c * 8);
        }
        asm volatile("cp.async.commit_group;");
    }

    int st = 0, st2 = 2;
    for (int it = 0; it < 16; it++) {
        asm volatile("cp.async.wait_group 1;" ::: "memory");
        __syncthreads();

        if (it + 2 < 16) {
            const int k0 = (it + 2) * 64;
            const unsigned soff = st2 * (QSTG * 2);
#pragma unroll
            for (int c = 0; c < 4; c++) {
                cpa16(xdst + soff + c * 16, X + xrow + k0 + c * 8);
                cpa16(wdst + soff + c * 16, W + wrow + k0 + c * 8);
            }
        }
        asm volatile("cp.async.commit_group;");

        const unsigned sa = st * (QSTG * 2);
#pragma unroll
        for (int ks = 0; ks < 4; ks++) {
            unsigned a0[4], a1[4];
            ldsm4(a0[0], a0[1], a0[2], a0[3], xa0 + sa + ks * 32);
            ldsm4(a1[0], a1[1], a1[2], a1[3], xa1 + sa + ks * 32);
#pragma unroll
            for (int j = 0; j < 4; j++) {
                unsigned b[4];
                ldsm4(b[0], b[1], b[2], b[3], wbb + sa + j * (16 * QST * 2) + ks * 32);
                mma16(acc[0][2 * j], a0, b[0], b[1]);
                mma16(acc[0][2 * j + 1], a0, b[2], b[3]);
                mma16(acc[1][2 * j], a1, b[0], b[1]);
                mma16(acc[1][2 * j + 1], a1, b[2], b[3]);
            }
        }
        st = (st == 2) ? 0 : st + 1;
        st2 = (st2 == 2) ? 0 : st2 + 1;
    }

    // epilogue: bias + relu + fp16 store (+ V column sums for z==2)
    const int vb2 = obase >> 11;
#pragma unroll
    for (int nt = 0; nt < 8; nt++) {
        int n = bn + n0 + 8 * nt + 2 * tig;
        float b0 = __ldg(&bias[n]), b1 = __ldg(&bias[n + 1]);
        float cs0 = 0.0f, cs1 = 0.0f;
#pragma unroll
        for (int mt = 0; mt < 2; mt++) {
            int m = obase + m0 + 16 * mt + g;
            float v0 = acc[mt][nt][0] + b0, v1 = acc[mt][nt][1] + b1;
            v0 = v0 > 0.f ? v0 : 0.f;
            v1 = v1 > 0.f ? v1 : 0.f;
            *(__half2*)&out[(size_t)m * 1024 + n] = __floats2half2_rn(v0, v1);
            float v2 = acc[mt][nt][2] + b0, v3 = acc[mt][nt][3] + b1;
            v2 = v2 > 0.f ? v2 : 0.f;
            v3 = v3 > 0.f ? v3 : 0.f;
            *(__half2*)&out[(size_t)(m + 8) * 1024 + n] = __floats2half2_rn(v2, v3);
            cs0 += v0 + v2;
            cs1 += v1 + v3;
        }
        if (z == 2) {
#pragma unroll
            for (int o = 4; o < 32; o <<= 1) {
                cs0 += __shfl_xor_sync(0xffffffffu, cs0, o);
                cs1 += __shfl_xor_sync(0xffffffffu, cs1, o);
            }
            if (g == 0) {
                atomicAdd(&g_vsum[vb2][n], cs0);
                atomicAdd(&g_vsum[vb2][n + 1], cs1);
            }
        }
    }
}

// =====================================================================
// PRE-FILL the entire output with mean(V)+residual, coalesced float4.
// grid (16h, BB, 32 row-slices of 4), 256 thr. attn overwrites later.
// =====================================================================
__global__ void __launch_bounds__(256) vfill_kernel(const float* __restrict__ queries,
                                                    float* __restrict__ out) {
    __shared__ float mean[64];
    const int h = blockIdx.x, b = blockIdx.y, sl = blockIdx.z;
    const int tid = threadIdx.x;

    if (tid < 64) mean[tid] = g_vsum[b][h * 64 + tid] * (1.0f / 2048.0f);
    __syncthreads();

    const int c4 = tid * 4;
#pragma unroll
    for (int r = 0; r < 4; r++) {
        const int rr = 4 * sl + r;           // 0..127 within this head's rows
        const int srow = 128 * h + rr;       // rr = 2d + e
        const float mv = mean[rr >> 1];
        const size_t off = (size_t)(b * 2048 + srow) * 1024 + c4;
        float4 qv = *(const float4*)&queries[off];
        *(float4*)&out[off] = make_float4(qv.x + mv, qv.y + mv, qv.z + mv, qv.w + mv);
    }
}

// =====================================================================
// Flash attention over COMPACTED unmasked queries; row-major scattered
// epilogue (warp writes one output row per step) overwrites pre-fill.
// =====================================================================
#define KST 72
#define OST 68
#define STAGE_H (64 * KST)
#define ATTN_SMEM ((6 * STAGE_H + 128 * KST) * 2)

__global__ void __launch_bounds__(256) attn_mma(const float* __restrict__ queries,
                                                float* __restrict__ out) {
    const int b = blockIdx.z, h = blockIdx.y;
    const int q0 = blockIdx.x * 128;
    const int nu = g_ncnt[b];
    if (q0 >= nu) return;  // inactive tile

    extern __shared__ __align__(16) char smbase[];
    __half* KB = (__half*)smbase;
    __half* VB = (__half*)smbase + 3 * STAGE_H;
    __half* Qs = (__half*)smbase + 6 * STAGE_H;
    float* So = (float*)smbase;
    __shared__ int sidx[128];

    const int tid = threadIdx.x;
    const int warp = tid >> 5, lane = tid & 31;
    const int g = lane >> 2, tig = lane & 3;
    const int qw = warp * 16;

    if (tid < 128) sidx[tid] = (q0 + tid < nu) ? g_qidx[b][q0 + tid] : -1;

    const int crow = tid >> 2;
    const int ccol = (tid & 3) * 16;
    const unsigned kdst = sptr(&KB[crow * KST + ccol]);
    const unsigned vdst = sptr(&VB[crow * KST + ccol]);

#pragma unroll
    for (int p = 0; p < 2; p++) {
        const size_t gofs = (size_t)(b * 2048 + p * 64 + crow) * 1024 + h * 64 + ccol;
        const unsigned soff = p * (STAGE_H * 2);
        cpa16(kdst + soff, g_K + gofs);
        cpa16(kdst + soff + 16, g_K + gofs + 8);
        cpa16(vdst + soff, g_V + gofs);
        cpa16(vdst + soff + 16, g_V + gofs + 8);
        asm volatile("cp.async.commit_group;");
    }

    // stage Q (compacted rows; scaled by 0.125*log2e), frags to registers
    {
        int row = tid >> 1;
        int koff = (tid & 1) * 32;
        const __half* qsrc = g_Q + (size_t)(b * 2048 + q0 + row) * 1024 + h * 64 + koff;
        const float qs = 0.125f * 1.4426950408889634f;
        const __half2 sc = __floats2half2_rn(qs, qs);
        __half2 v[16];
        *(uint4*)&v[0] = *(const uint4*)&qsrc[0];
        *(uint4*)&v[4] = *(const uint4*)&qsrc[8];
        *(uint4*)&v[8] = *(const uint4*)&qsrc[16];
        *(uint4*)&v[12] = *(const uint4*)&qsrc[24];
#pragma unroll
        for (int j = 0; j < 16; j++) v[j] = __hmul2(v[j], sc);
        *(uint4*)&Qs[row * KST + koff] = *(uint4*)&v[0];
        *(uint4*)&Qs[row * KST + koff + 8] = *(uint4*)&v[4];
        *(uint4*)&Qs[row * KST + koff + 16] = *(uint4*)&v[8];
        *(uint4*)&Qs[row * KST + koff + 24] = *(uint4*)&v[12];
    }
    __syncwarp();
    unsigned qf[4][4];
    {
        unsigned qa = sptr(&Qs[(qw + (lane & 15)) * KST + (lane >> 4) * 8]);
#pragma unroll
        for (int ks = 0; ks < 4; ks++)
            ldsm4(qf[ks][0], qf[ks][1], qf[ks][2], qf[ks][3], qa + ks * 32);
    }

    float mA = -1e30f, mB = -1e30f, lA = 0.0f, lB = 0.0f;
    float o[8][4];
#pragma unroll
    for (int nt = 0; nt < 8; nt++)
#pragma unroll
        for (int i = 0; i < 4; i++) o[nt][i] = 0.0f;

    const unsigned kb0 = sptr(&KB[(8 * (lane >> 4) + (lane & 7)) * KST + ((lane >> 3) & 1) * 8]);
    const unsigned vb0 = sptr(&VB[(8 * ((lane >> 3) & 1) + (lane & 7)) * KST + (lane >> 4) * 8]);

    int st = 0, st2 = 2;
    for (int jt = 0; jt < 32; jt++) {
        asm volatile("cp.async.wait_group 1;" ::: "memory");
        __syncthreads();

        if (jt + 2 < 32) {
            const size_t gofs = (size_t)(b * 2048 + (jt + 2) * 64 + crow) * 1024 + h * 64 + ccol;
            const unsigned soff = st2 * (STAGE_H * 2);
            cpa16(kdst + soff, g_K + gofs);
            cpa16(kdst + soff + 16, g_K + gofs + 8);
            cpa16(vdst + soff, g_V + gofs);
            cpa16(vdst + soff + 16, g_V + gofs + 8);
        }
        asm volatile("cp.async.commit_group;");

        const unsigned kb = kb0 + st * (STAGE_H * 2);
        float s[8][4];
#pragma unroll
        for (int nt = 0; nt < 8; nt++)
#pragma unroll
            for (int i = 0; i < 4; i++) s[nt][i] = 0.0f;
#pragma unroll
        for (int ks = 0; ks < 4; ks++) {
#pragma unroll
            for (int j = 0; j < 4; j++) {
                unsigned bfr[4];
                ldsm4(bfr[0], bfr[1], bfr[2], bfr[3], kb + j * (16 * KST * 2) + ks * 32);
                mma16(s[2 * j], qf[ks], bfr[0], bfr[1]);
                mma16(s[2 * j + 1], qf[ks], bfr[2], bfr[3]);
            }
        }

        float mxA = s[0][0], mxB = s[0][2];
#pragma unroll
        for (int nt = 0; nt < 8; nt++) {
            mxA = fmaxf(mxA, fmaxf(s[nt][0], s[nt][1]));
            mxB = fmaxf(mxB, fmaxf(s[nt][2], s[nt][3]));
        }
        mxA = fmaxf(mxA, __shfl_xor_sync(0xffffffffu, mxA, 1));
        mxA = fmaxf(mxA, __shfl_xor_sync(0xffffffffu, mxA, 2));
        mxB = fmaxf(mxB, __shfl_xor_sync(0xffffffffu, mxB, 1));
        mxB = fmaxf(mxB, __shfl_xor_sync(0xffffffffu, mxB, 2));
        float mnA = fmaxf(mA, mxA), mnB = fmaxf(mB, mxB);
        float cA = ex2(mA - mnA), cB = ex2(mB - mnB);
        mA = mnA; mB = mnB;
        float sumA = 0.0f, sumB = 0.0f;
#pragma unroll
        for (int nt = 0; nt < 8; nt++) {
            s[nt][0] = ex2(s[nt][0] - mnA);
            s[nt][1] = ex2(s[nt][1] - mnA);
            s[nt][2] = ex2(s[nt][2] - mnB);
            s[nt][3] = ex2(s[nt][3] - mnB);
            sumA += s[nt][0] + s[nt][1];
            sumB += s[nt][2] + s[nt][3];
        }
        sumA += __shfl_xor_sync(0xffffffffu, sumA, 1);
        sumA += __shfl_xor_sync(0xffffffffu, sumA, 2);
        sumB += __shfl_xor_sync(0xffffffffu, sumB, 1);
        sumB += __shfl_xor_sync(0xffffffffu, sumB, 2);
        lA = lA * cA + sumA;
        lB = lB * cB + sumB;

#pragma unroll
        for (int nt = 0; nt < 8; nt++) {
            o[nt][0] *= cA; o[nt][1] *= cA;
            o[nt][2] *= cB; o[nt][3] *= cB;
        }
        const unsigned vb = vb0 + st * (STAGE_H * 2);
#pragma unroll
        for (int ks = 0; ks < 4; ks++) {
            unsigned pa[4];
            pa[0] = h2u(s[2 * ks][0], s[2 * ks][1]);
            pa[1] = h2u(s[2 * ks][2], s[2 * ks][3]);
            pa[2] = h2u(s[2 * ks + 1][0], s[2 * ks + 1][1]);
            pa[3] = h2u(s[2 * ks + 1][2], s[2 * ks + 1][3]);
#pragma unroll
            for (int j = 0; j < 4; j++) {
                unsigned vfr[4];
                ldsm4t(vfr[0], vfr[1], vfr[2], vfr[3], vb + ks * (16 * KST * 2) + j * 32);
                mma16(o[2 * j], pa, vfr[0], vfr[1]);
                mma16(o[2 * j + 1], pa, vfr[2], vfr[3]);
            }
        }
        st = (st == 2) ? 0 : st + 1;
        st2 = (st2 == 2) ? 0 : st2 + 1;
    }

    __syncthreads();
    {
        float rA = 1.0f / lA, rB = 1.0f / lB;
#pragma unroll
        for (int nt = 0; nt < 8; nt++) {
            *(float2*)&So[(qw + g) * OST + 8 * nt + 2 * tig] =
                make_float2(o[nt][0] * rA, o[nt][1] * rA);
            *(float2*)&So[(qw + g + 8) * OST + 8 * nt + 2 * tig] =
                make_float2(o[nt][2] * rB, o[nt][3] * rB);
        }
    }
    __syncthreads();

    // row-major scattered reshape + residual (overwrites pre-filled mean):
    //   thread owns query i = tid&127; loops over dd. Each warp step writes
    //   ONE output row with ascending (gappy) columns -> few sectors.
    {
        const int ii = tid & 127;
        const int ddb = (tid >> 7) * 32;  // dd base: 0 or 32
        const int q = sidx[ii];
        if (q >= 0) {
            const int col = q & 1023;
            const int e = q >> 10;
            const size_t base = (size_t)(b * 2048 + 128 * h + e) * 1024 + col;
#pragma unroll 8
            for (int t = 0; t < 32; t++) {
                const int dd = ddb + t;
                const size_t off = base + (size_t)(2 * dd) * 1024;
                out[off] = So[ii * OST + dd] + queries[off];
            }
        }
    }
}

// ---------------- launch ----------------
extern "C" void kernel_launch(void* const* d_in, const int* in_sizes, int n_in, void* d_out,
                              int out_size) {
    const float* queries = (const float*)d_in[0];
    const float* keys = (const float*)d_in[1];
    const float* values = (const float*)d_in[2];
    const int* amask = (const int*)d_in[3];
    const float* Wq = (const float*)d_in[4];
    const float* bq = (const float*)d_in[5];
    const float* Wk = (const float*)d_in[6];
    const float* bk = (const float*)d_in[7];
    const float* Wv = (const float*)d_in[8];
    const float* bv = (const float*)d_in[9];
    float* out = (float*)d_out;

    compact_kernel<<<BB, 32>>>(amask);  // also zeros g_vsum

    dim3 gc(512, 6, 1);
    cvt_kernel<<<gc, 256>>>(queries, keys, values, Wq, Wk, Wv);

    cudaFuncSetAttribute(qkv_gemm, cudaFuncAttributeMaxDynamicSharedMemorySize, GEMM_SMEM);
    dim3 g1(8, 32, 3);
    qkv_gemm<<<g1, 256, GEMM_SMEM>>>(bq, bk, bv);  // V slice also fills g_vsum

    vfill_kernel<<<dim3(16, BB, 32), 256>>>(queries, out);  // pre-fill ALL of out

    cudaFuncSetAttribute(attn_mma, cudaFuncAttributeMaxDynamicSharedMemorySize, ATTN_SMEM);
    dim3 g2(16, 16, BB);
    attn_mma<<<g2, 256, ATTN_SMEM>>>(queries, out);  // overwrites unmasked positions
}